// round 16
// baseline (speedup 1.0000x reference)
#include <cuda_runtime.h>
#include <cuda_fp16.h>
#include <math.h>
#include <stdint.h>

#define Bq   4
#define Sq   1024
#define Dq   1024
#define Hh   16
#define HD   64
#define Ll   2
#define Ee   8
#define DFFq 4096
#define TOK  (Bq*Sq)   // 4096

// ---------------- static scratch ---------------------------------------------
__device__ float g_X[TOK*Dq];
__device__ float g_H[TOK*Dq];
__device__ float g_Q[TOK*Dq];          // layer-0 (fp32, split path)
__device__ float g_K[TOK*Dq];
__device__ float g_V[TOK*Dq];
__device__ float g_Y[TOK*Dq];
__device__ __half g_Qh[TOK*Dq];        // layer-1 (fp16 path)
__device__ __half g_Kh[TOK*Dq];
__device__ __half g_Vh[TOK*Dq];
__device__ __half g_Yh[TOK*Dq];
__device__ __half g_hidden_h[(size_t)Ee*TOK*DFFq];   // 256MB fp16
__device__ float g_moeout[(size_t)Ee*TOK*Dq];
__device__ int   g_counts[Ee];
__device__ int   g_tok[Ee*TOK];
__device__ float g_wt[Ee*TOK];
__device__ int   g_islot[TOK*2];
__device__ int   g_bsel[Bq*2];
__device__ float g_bw[Bq*2];
__device__ float g_xmean[Bq*Dq];

// ---------------- helpers ----------------------------------------------------
__device__ __forceinline__ void top2_of8(const float* lg, int& i1, int& i2,
                                         float& w1, float& w2) {
    i1 = 0; float v1 = lg[0];
#pragma unroll
    for (int e = 1; e < Ee; e++) if (lg[e] > v1) { v1 = lg[e]; i1 = e; }
    i2 = -1; float v2 = -3.0e38f;
#pragma unroll
    for (int e = 0; e < Ee; e++) if (e != i1 && lg[e] > v2) { v2 = lg[e]; i2 = e; }
    float ex = expf(v2 - v1);
    w1 = 1.0f / (1.0f + ex);
    w2 = ex / (1.0f + ex);
}
__device__ __forceinline__ float gelu_exact(float x) {
    return 0.5f * x * (1.0f + erff(x * 0.7071067811865476f));
}
__device__ __forceinline__ void mma_f16(float c[4], const uint32_t a[4],
                                        const uint32_t b[2]) {
    asm volatile(
        "mma.sync.aligned.m16n8k16.row.col.f32.f16.f16.f32 "
        "{%0,%1,%2,%3},{%4,%5,%6,%7},{%8,%9},{%0,%1,%2,%3};"
        : "+f"(c[0]), "+f"(c[1]), "+f"(c[2]), "+f"(c[3])
        : "r"(a[0]), "r"(a[1]), "r"(a[2]), "r"(a[3]), "r"(b[0]), "r"(b[1]));
}
__device__ __forceinline__ uint32_t pack_h2(__half a, __half b) {
    __half2 h = __halves2half2(a, b);
    return *(uint32_t*)&h;
}
__device__ __forceinline__ uint32_t pack_f2h(float a, float b) {
    return pack_h2(__float2half_rn(a), __float2half_rn(b));
}

// ---------------- simple kernels ---------------------------------------------
__global__ void copy_in_kernel(const float* __restrict__ src) {
    int i = blockIdx.x * 256 + threadIdx.x;
    g_X[i] = src[i];
}

// ln2 variant also zeroes MoE counts (consumed by the NEXT launch, gate/assign)
template<int ZERO_CNT>
__global__ void ln_kernel_t(const float* __restrict__ w, const float* __restrict__ b) {
    if (ZERO_CNT && blockIdx.x == 0 && threadIdx.x < Ee) g_counts[threadIdx.x] = 0;
    int t = blockIdx.x, tid = threadIdx.x;
    const float* xr = g_X + (size_t)t * Dq;
    float s = 0.f, s2 = 0.f;
    for (int d = tid; d < Dq; d += 256) { float v = xr[d]; s += v; s2 += v * v; }
    __shared__ float r1[256], r2[256];
    r1[tid] = s; r2[tid] = s2; __syncthreads();
    for (int off = 128; off; off >>= 1) {
        if (tid < off) { r1[tid] += r1[tid + off]; r2[tid] += r2[tid + off]; }
        __syncthreads();
    }
    float mean = r1[0] * (1.0f / Dq);
    float var  = r2[0] * (1.0f / Dq) - mean * mean;
    float rstd = rsqrtf(var + 1e-5f);
    float* hr = g_H + (size_t)t * Dq;
    for (int d = tid; d < Dq; d += 256)
        hr[d] = (xr[d] - mean) * rstd * w[d] + b[d];
}

__global__ void ln_combine_kernel(const float* __restrict__ w, const float* __restrict__ b) {
    int t = blockIdx.x, tid = threadIdx.x;
    int s0 = g_islot[t * 2], s1 = g_islot[t * 2 + 1];
    float* xr = g_X + (size_t)t * Dq;
    const float* m0 = g_moeout + (size_t)s0 * Dq;
    const float* m1 = g_moeout + (size_t)s1 * Dq;
    float s = 0.f, s2 = 0.f;
    for (int d = tid; d < Dq; d += 256) {
        float v = xr[d] + m0[d] + m1[d];
        xr[d] = v;
        s += v; s2 += v * v;
    }
    __shared__ float r1[256], r2[256];
    r1[tid] = s; r2[tid] = s2; __syncthreads();
    for (int off = 128; off; off >>= 1) {
        if (tid < off) { r1[tid] += r1[tid + off]; r2[tid] += r2[tid + off]; }
        __syncthreads();
    }
    float mean = r1[0] * (1.0f / Dq);
    float var  = r2[0] * (1.0f / Dq) - mean * mean;
    float rstd = rsqrtf(var + 1e-5f);
    float* hr = g_H + (size_t)t * Dq;
    for (int d = tid; d < Dq; d += 256)
        hr[d] = (xr[d] - mean) * rstd * w[d] + b[d];
}

__global__ void combine_out_kernel(float* __restrict__ dst) {
    int i = blockIdx.x * 256 + threadIdx.x;
    int t = i >> 8;
    int c4 = (i & 255) << 2;
    int s0 = g_islot[t * 2], s1 = g_islot[t * 2 + 1];
    float4 a = *(const float4*)&g_moeout[(size_t)s0 * Dq + c4];
    float4 b = *(const float4*)&g_moeout[(size_t)s1 * Dq + c4];
    float4 x = *(const float4*)&g_X[(size_t)t * Dq + c4];
    x.x += a.x + b.x; x.y += a.y + b.y; x.z += a.z + b.z; x.w += a.w + b.w;
    *(float4*)&dst[(size_t)t * Dq + c4] = x;
}

// ---------------- fp16 3-pass split GEMM (layer-0, 128x128, BK=32) -----------
#define T2W 136
#define T2SZ (16*T2W)
#define H3BUF (4*T2SZ)
#define SMEM_H3 (2*H3BUF*4)           // 69632 B

template<int MODE>
__global__ void __launch_bounds__(512, 1)
gemm_h3(const float* __restrict__ A,
        const float* __restrict__ W0, const float* __restrict__ W1,
        const float* __restrict__ W2,
        const float* __restrict__ b0, const float* __restrict__ b1,
        const float* __restrict__ b2,
        float* __restrict__ C0, float* __restrict__ C1, float* __restrict__ C2,
        int Kd, int N) {
    extern __shared__ uint32_t tiles[];
    int z = (MODE == 0) ? blockIdx.z : 0;
    const float* Wall = (z == 0) ? W0 : (z == 1 ? W1 : W2);
    const float* bias = (z == 0) ? b0 : (z == 1 ? b1 : b2);
    float* Cp         = (z == 0) ? C0 : (z == 1 ? C1 : C2);

    int tid = threadIdx.x;
    int rowBase = blockIdx.y * 128, colBase = blockIdx.x * 128;

    int lrA = tid >> 2, kcA4 = (tid & 3) << 2, kpA = (tid & 3) << 1;
    const float* Ap = A + (size_t)(rowBase + lrA) * Kd + kcA4;
    int kpB = tid >> 6, nB = (tid & 63) << 1;
    const float* Wp = Wall + (size_t)(2 * kpB) * N + colBase + nB;

    int lane = tid & 31, warp = tid >> 5;
    int wm = (warp & 3) * 32, wn = (warp >> 2) * 32;
    int gid = lane >> 2, tig = lane & 3;

    float acc[2][4][4];
#pragma unroll
    for (int a = 0; a < 2; a++)
#pragma unroll
        for (int b3 = 0; b3 < 4; b3++)
#pragma unroll
            for (int c = 0; c < 4; c++) acc[a][b3][c] = 0.f;

    int nk = Kd / 32;
    float4 av0, av1;
    float2 br0, br1, br2, br3;
    av0 = *(const float4*)(Ap);
    av1 = *(const float4*)(Ap + 16);
    br0 = *(const float2*)(Wp);
    br1 = *(const float2*)(Wp + N);
    br2 = *(const float2*)(Wp + (size_t)16 * N);
    br3 = *(const float2*)(Wp + (size_t)17 * N);

#define H3_STORE(BUF)                                                          \
    {                                                                          \
        uint32_t* Ahi = (BUF);                                                 \
        uint32_t* Alo = (BUF) + T2SZ;                                          \
        uint32_t* Bhi = (BUF) + 2 * T2SZ;                                      \
        uint32_t* Blo = (BUF) + 3 * T2SZ;                                      \
        __half h0 = __float2half_rn(av0.x), h1 = __float2half_rn(av0.y);       \
        __half h2 = __float2half_rn(av0.z), h3 = __float2half_rn(av0.w);       \
        Ahi[kpA * T2W + lrA]       = pack_h2(h0, h1);                          \
        Ahi[(kpA + 1) * T2W + lrA] = pack_h2(h2, h3);                          \
        Alo[kpA * T2W + lrA]       = pack_f2h(av0.x - __half2float(h0), av0.y - __half2float(h1)); \
        Alo[(kpA + 1) * T2W + lrA] = pack_f2h(av0.z - __half2float(h2), av0.w - __half2float(h3)); \
        __half g0 = __float2half_rn(av1.x), g1 = __float2half_rn(av1.y);       \
        __half g2 = __float2half_rn(av1.z), g3 = __float2half_rn(av1.w);       \
        Ahi[(kpA + 8) * T2W + lrA] = pack_h2(g0, g1);                          \
        Ahi[(kpA + 9) * T2W + lrA] = pack_h2(g2, g3);                          \
        Alo[(kpA + 8) * T2W + lrA] = pack_f2h(av1.x - __half2float(g0), av1.y - __half2float(g1)); \
        Alo[(kpA + 9) * T2W + lrA] = pack_f2h(av1.z - __half2float(g2), av1.w - __half2float(g3)); \
        __half w00 = __float2half_rn(br0.x), w10 = __float2half_rn(br1.x);     \
        __half w01 = __float2half_rn(br0.y), w11 = __float2half_rn(br1.y);     \
        Bhi[kpB * T2W + nB]     = pack_h2(w00, w10);                           \
        Bhi[kpB * T2W + nB + 1] = pack_h2(w01, w11);                           \
        Blo[kpB * T2W + nB]     = pack_f2h(br0.x - __half2float(w00), br1.x - __half2float(w10)); \
        Blo[kpB * T2W + nB + 1] = pack_f2h(br0.y - __half2float(w01), br1.y - __half2float(w11)); \
        __half u00 = __float2half_rn(br2.x), u10 = __float2half_rn(br3.x);     \
        __half u01 = __float2half_rn(br2.y), u11 = __float2half_rn(br3.y);     \
        Bhi[(kpB + 8) * T2W + nB]     = pack_h2(u00, u10);                     \
        Bhi[(kpB + 8) * T2W + nB + 1] = pack_h2(u01, u11);                     \
        Blo[(kpB + 8) * T2W + nB]     = pack_f2h(br2.x - __half2float(u00), br3.x - __half2float(u10)); \
        Blo[(kpB + 8) * T2W + nB + 1] = pack_f2h(br2.y - __half2float(u01), br3.y - __half2float(u11)); \
    }

    H3_STORE(tiles);
    __syncthreads();

    for (int t = 0; t < nk; t++) {
        if (t + 1 < nk) {
            const float* a2 = Ap + (size_t)(t + 1) * 32;
            av0 = *(const float4*)(a2);
            av1 = *(const float4*)(a2 + 16);
            const float* w2 = Wp + (size_t)(t + 1) * 32 * N;
            br0 = *(const float2*)(w2);
            br1 = *(const float2*)(w2 + N);
            br2 = *(const float2*)(w2 + (size_t)16 * N);
            br3 = *(const float2*)(w2 + (size_t)17 * N);
        }
        int s = t & 1;
        const uint32_t* Ahi = tiles + s * H3BUF;
        const uint32_t* Alo = Ahi + T2SZ;
        const uint32_t* Bhi = Ahi + 2 * T2SZ;
        const uint32_t* Blo = Ahi + 3 * T2SZ;

#pragma unroll
        for (int sub = 0; sub < 2; sub++) {
            int ko = sub * 8;
            uint32_t ah[2][4], al[2][4], bh[4][2], bl[4][2];
#pragma unroll
            for (int mt = 0; mt < 2; mt++) {
                int m0 = wm + mt * 16 + gid;
                ah[mt][0] = Ahi[(ko + tig) * T2W + m0];
                ah[mt][1] = Ahi[(ko + tig) * T2W + m0 + 8];
                ah[mt][2] = Ahi[(ko + tig + 4) * T2W + m0];
                ah[mt][3] = Ahi[(ko + tig + 4) * T2W + m0 + 8];
                al[mt][0] = Alo[(ko + tig) * T2W + m0];
                al[mt][1] = Alo[(ko + tig) * T2W + m0 + 8];
                al[mt][2] = Alo[(ko + tig + 4) * T2W + m0];
                al[mt][3] = Alo[(ko + tig + 4) * T2W + m0 + 8];
            }
#pragma unroll
            for (int nt = 0; nt < 4; nt++) {
                int n0 = wn + nt * 8 + gid;
                bh[nt][0] = Bhi[(ko + tig) * T2W + n0];
                bh[nt][1] = Bhi[(ko + tig + 4) * T2W + n0];
                bl[nt][0] = Blo[(ko + tig) * T2W + n0];
                bl[nt][1] = Blo[(ko + tig + 4) * T2W + n0];
            }
#pragma unroll
            for (int mt = 0; mt < 2; mt++)
#pragma unroll
                for (int nt = 0; nt < 4; nt++)
                    mma_f16(acc[mt][nt], ah[mt], bh[nt]);
#pragma unroll
            for (int mt = 0; mt < 2; mt++)
#pragma unroll
                for (int nt = 0; nt < 4; nt++)
                    mma_f16(acc[mt][nt], ah[mt], bl[nt]);
#pragma unroll
            for (int mt = 0; mt < 2; mt++)
#pragma unroll
                for (int nt = 0; nt < 4; nt++)
                    mma_f16(acc[mt][nt], al[mt], bh[nt]);
        }

        if (t + 1 < nk) {
            uint32_t* nb = tiles + (s ^ 1) * H3BUF;
            H3_STORE(nb);
        }
        __syncthreads();
    }
#undef H3_STORE

#pragma unroll
    for (int mt = 0; mt < 2; mt++) {
#pragma unroll
        for (int c = 0; c < 4; c++) {
            int r = rowBase + wm + mt * 16 + gid + ((c & 2) ? 8 : 0);
#pragma unroll
            for (int nt = 0; nt < 4; nt++) {
                int cg = colBase + wn + nt * 8 + tig * 2 + (c & 1);
                float v = acc[mt][nt][c] + bias[cg];
                if (MODE == 1) v += Cp[(size_t)r * N + cg];
                Cp[(size_t)r * N + cg] = v;
            }
        }
    }
}

// ---------------- fp16 1-pass big-tile GEMM (128x256, BK=32, 512 thr) --------
#define HB_AW 136
#define HB_BW 264
#define HB_AT (16*HB_AW)
#define HB_BT (16*HB_BW)
#define HB_BUF (HB_AT+HB_BT)
#define SMEM_HB ((256 + 2*HB_BUF) * 4)   // 52224 B

template<int MODE>
__global__ void __launch_bounds__(512, 1)
gemm_hb(const void* __restrict__ A,
        const float* __restrict__ W0, const float* __restrict__ W1,
        const float* __restrict__ W2,
        const float* __restrict__ b0, const float* __restrict__ b1,
        const float* __restrict__ b2,
        void* __restrict__ C0, void* __restrict__ C1, void* __restrict__ C2,
        int Kd, int N, int layer) {
    constexpr bool A_HALF   = (MODE == 1 || MODE == 3);
    constexpr bool OUT_HALF = (MODE == 0 || MODE == 2);
    extern __shared__ float smf[];
    int*   s_tok = (int*)smf;
    float* s_wt  = smf + 128;
    uint32_t* tiles = (uint32_t*)(smf + 256);

    int tid = threadIdx.x;
    int rowBase = blockIdx.y * 128, colBase = blockIdx.x * 256;

    int e = 0, cnt = 0;
    const float* W;
    const float* bias;
    int z = 0;
    if (MODE >= 2) {
        e = blockIdx.z;
        cnt = g_counts[e];
        if (rowBase >= cnt) return;
        W    = W0 + (size_t)(layer * Ee + e) * Kd * N;
        bias = b0 + (size_t)(layer * Ee + e) * N;
        if (tid < 128) {
            int r = rowBase + tid;
            int rc = r < cnt ? r : cnt - 1;
            s_tok[tid] = g_tok[e * TOK + rc];
            s_wt[tid]  = g_wt [e * TOK + rc];
        }
        __syncthreads();
    } else {
        z = (MODE == 0) ? blockIdx.z : 0;
        W    = (z == 0) ? W0 : (z == 1 ? W1 : W2);
        bias = (z == 0) ? b0 : (z == 1 ? b1 : b2);
    }

    int lrA = tid >> 2, kcA4 = (tid & 3) << 2, kpA = (tid & 3) << 1;
    const float*  Apf = nullptr;
    const __half* Aph = nullptr;
    if (MODE == 2)      Apf = g_H + (size_t)s_tok[lrA] * Kd + kcA4;
    else if (MODE == 3) Aph = g_hidden_h + ((size_t)e * TOK + rowBase + lrA) * Kd + kcA4;
    else if (MODE == 1) Aph = (const __half*)A + (size_t)(rowBase + lrA) * Kd + kcA4;
    else                Apf = (const float*)A + (size_t)(rowBase + lrA) * Kd + kcA4;

    int kpB = tid >> 6, nB4 = (tid & 63) << 2;
    const float* Wp = W + (size_t)(2 * kpB) * N + colBase + nB4;

    int lane = tid & 31, warp = tid >> 5;
    int wm = (warp & 1) * 64, wn = (warp >> 1) * 32;
    int gid = lane >> 2, tig = lane & 3;

    float acc[4][4][4];
#pragma unroll
    for (int a = 0; a < 4; a++)
#pragma unroll
        for (int b3 = 0; b3 < 4; b3++)
#pragma unroll
            for (int c = 0; c < 4; c++) acc[a][b3][c] = 0.f;

    int nk = Kd / 32;
    float4 av0, av1, bv0, bv1, bv2, bv3;
    uint2 au0, au1;
    if (A_HALF) {
        au0 = *(const uint2*)(Aph);
        au1 = *(const uint2*)(Aph + 16);
    } else {
        av0 = *(const float4*)(Apf);
        av1 = *(const float4*)(Apf + 16);
    }
    bv0 = *(const float4*)(Wp);
    bv1 = *(const float4*)(Wp + N);
    bv2 = *(const float4*)(Wp + (size_t)16 * N);
    bv3 = *(const float4*)(Wp + (size_t)17 * N);

#define HB_STORE(BUF)                                                          \
    {                                                                          \
        uint32_t* As = (BUF);                                                  \
        uint32_t* Bs = (BUF) + HB_AT;                                          \
        if (A_HALF) {                                                          \
            As[kpA * HB_AW + lrA]       = au0.x;                               \
            As[(kpA + 1) * HB_AW + lrA] = au0.y;                               \
            As[(kpA + 8) * HB_AW + lrA] = au1.x;                               \
            As[(kpA + 9) * HB_AW + lrA] = au1.y;                               \
        } else {                                                               \
            As[kpA * HB_AW + lrA]       = pack_f2h(av0.x, av0.y);              \
            As[(kpA + 1) * HB_AW + lrA] = pack_f2h(av0.z, av0.w);              \
            As[(kpA + 8) * HB_AW + lrA] = pack_f2h(av1.x, av1.y);              \
            As[(kpA + 9) * HB_AW + lrA] = pack_f2h(av1.z, av1.w);              \
        }                                                                      \
        Bs[kpB * HB_BW + nB4 + 0] = pack_f2h(bv0.x, bv1.x);                    \
        Bs[kpB * HB_BW + nB4 + 1] = pack_f2h(bv0.y, bv1.y);                    \
        Bs[kpB * HB_BW + nB4 + 2] = pack_f2h(bv0.z, bv1.z);                    \
        Bs[kpB * HB_BW + nB4 + 3] = pack_f2h(bv0.w, bv1.w);                    \
        Bs[(kpB + 8) * HB_BW + nB4 + 0] = pack_f2h(bv2.x, bv3.x);              \
        Bs[(kpB + 8) * HB_BW + nB4 + 1] = pack_f2h(bv2.y, bv3.y);              \
        Bs[(kpB + 8) * HB_BW + nB4 + 2] = pack_f2h(bv2.z, bv3.z);              \
        Bs[(kpB + 8) * HB_BW + nB4 + 3] = pack_f2h(bv2.w, bv3.w);              \
    }

    HB_STORE(tiles);
    __syncthreads();

    for (int t = 0; t < nk; t++) {
        if (t + 1 < nk) {
            if (A_HALF) {
                au0 = *(const uint2*)(Aph + (size_t)(t + 1) * 32);
                au1 = *(const uint2*)(Aph + (size_t)(t + 1) * 32 + 16);
            } else {
                const float* a2 = Apf + (size_t)(t + 1) * 32;
                av0 = *(const float4*)(a2);
                av1 = *(const float4*)(a2 + 16);
            }
            const float* w2 = Wp + (size_t)(t + 1) * 32 * N;
            bv0 = *(const float4*)(w2);
            bv1 = *(const float4*)(w2 + N);
            bv2 = *(const float4*)(w2 + (size_t)16 * N);
            bv3 = *(const float4*)(w2 + (size_t)17 * N);
        }
        int s = t & 1;
        const uint32_t* As = tiles + s * HB_BUF;
        const uint32_t* Bs = As + HB_AT;

#pragma unroll
        for (int sub = 0; sub < 2; sub++) {
            int ko = sub * 8;
            uint32_t af[4][4], bf[4][2];
#pragma unroll
            for (int mt = 0; mt < 4; mt++) {
                int m0 = wm + mt * 16 + gid;
                af[mt][0] = As[(ko + tig) * HB_AW + m0];
                af[mt][1] = As[(ko + tig) * HB_AW + m0 + 8];
                af[mt][2] = As[(ko + tig + 4) * HB_AW + m0];
                af[mt][3] = As[(ko + tig + 4) * HB_AW + m0 + 8];
            }
#pragma unroll
            for (int nt = 0; nt < 4; nt++) {
                int n0 = wn + nt * 8 + gid;
                bf[nt][0] = Bs[(ko + tig) * HB_BW + n0];
                bf[nt][1] = Bs[(ko + tig + 4) * HB_BW + n0];
            }
#pragma unroll
            for (int mt = 0; mt < 4; mt++)
#pragma unroll
                for (int nt = 0; nt < 4; nt++)
                    mma_f16(acc[mt][nt], af[mt], bf[nt]);
        }

        if (t + 1 < nk) {
            uint32_t* nb = tiles + (s ^ 1) * HB_BUF;
            HB_STORE(nb);
        }
        __syncthreads();
    }
#undef HB_STORE

    if (OUT_HALF) {
        __half* outh = nullptr;
        if (MODE == 0) outh = (__half*)((z == 0) ? C0 : (z == 1 ? C1 : C2));
#pragma unroll
        for (int mt = 0; mt < 4; mt++) {
#pragma unroll
            for (int rp = 0; rp < 2; rp++) {
                int r = rowBase + wm + mt * 16 + gid + rp * 8;
                if (MODE == 2 && r >= cnt) continue;
#pragma unroll
                for (int nt = 0; nt < 4; nt++) {
                    int cg0 = colBase + wn + nt * 8 + tig * 2;
                    float v0 = acc[mt][nt][rp * 2]     + bias[cg0];
                    float v1 = acc[mt][nt][rp * 2 + 1] + bias[cg0 + 1];
                    if (MODE == 2) { v0 = gelu_exact(v0); v1 = gelu_exact(v1); }
                    uint32_t pk = pack_f2h(v0, v1);
                    if (MODE == 0)
                        *(uint32_t*)&outh[(size_t)r * N + cg0] = pk;
                    else
                        *(uint32_t*)&g_hidden_h[((size_t)e * TOK + r) * N + cg0] = pk;
                }
            }
        }
    } else {
        float* Cpf = (float*)C0;
#pragma unroll
        for (int mt = 0; mt < 4; mt++) {
#pragma unroll
            for (int c = 0; c < 4; c++) {
                int rl = wm + mt * 16 + gid + ((c & 2) ? 8 : 0);
                int r  = rowBase + rl;
#pragma unroll
                for (int nt = 0; nt < 4; nt++) {
                    int cg = colBase + wn + nt * 8 + tig * 2 + (c & 1);
                    float v = acc[mt][nt][c] + bias[cg];
                    if (MODE == 1) {
                        Cpf[(size_t)r * N + cg] = v + Cpf[(size_t)r * N + cg];
                    } else {
                        g_moeout[((size_t)(e * TOK + r)) * N + cg] = v * s_wt[rl];
                    }
                }
            }
        }
    }
}

// ---------------- fp16 split flash attention (layer 0, qb-paired) ------------
// Causal skip: MMA groups whose columns (QK) / k-range (PV) lie entirely above
// the warp's max row are skipped (bit-identical: masked or exact-zero adds).
#define FQ2 (32*136)
#define FK2 (32*72)
#define FV2 (32*72)
#define FP2 (32*136)
#define FL2_TOT (FQ2+FK2+FV2+FP2)
#define FL2_SMEM1 (FL2_TOT*8)

template<int SPLIT>
__global__ void __launch_bounds__(256, 2)
flash_h() {
    extern __shared__ uint32_t fu[];
    uint32_t* Qh = fu;
    uint32_t* Ql = Qh + FQ2;
    uint32_t* Kh = Qh + FQ2 * (SPLIT + 1);
    uint32_t* Kl = Kh + FK2;
    uint32_t* Vh = Kh + FK2 * (SPLIT + 1);
    uint32_t* Vl = Vh + FV2;
    uint32_t* Ph = Vh + FV2 * (SPLIT + 1);
    uint32_t* Pl = Ph + FP2;

    int h = blockIdx.y, b = blockIdx.z;
    int tid = threadIdx.x, warp = tid >> 5, lane = tid & 31;
    int gid = lane >> 2, tig = lane & 3;
    int mrow = warp * 16 + gid;

    for (int hf = 0; hf < 2; hf++) {
        int qb = (hf == 0) ? (7 - (int)blockIdx.x) : (int)blockIdx.x;
        int rowmax = qb * 128 + warp * 16 + 15;   // warp-uniform

        for (int i = tid; i < 2048; i += 256) {
            int r = i >> 4, d4 = (i & 15) << 2, dp = (i & 15) << 1;
            float4 v = *(const float4*)&g_Q[((size_t)(b * Sq + qb * 128 + r)) * Dq + h * HD + d4];
            __half h0 = __float2half_rn(v.x), h1 = __float2half_rn(v.y);
            __half h2 = __float2half_rn(v.z), h3 = __float2half_rn(v.w);
            Qh[dp * 136 + r]       = pack_h2(h0, h1);
            Qh[(dp + 1) * 136 + r] = pack_h2(h2, h3);
            if (SPLIT) {
                Ql[dp * 136 + r]       = pack_f2h(v.x - __half2float(h0), v.y - __half2float(h1));
                Ql[(dp + 1) * 136 + r] = pack_f2h(v.z - __half2float(h2), v.w - __half2float(h3));
            }
        }

        float mA = -1e30f, mB = -1e30f, lA = 0.f, lB = 0.f;
        float o[8][4];
#pragma unroll
        for (int nt = 0; nt < 8; nt++)
#pragma unroll
            for (int c = 0; c < 4; c++) o[nt][c] = 0.f;

        int nkt = 2 * qb + 2;
        for (int kt = 0; kt < nkt; kt++) {
            __syncthreads();
            for (int i = tid; i < 1024; i += 256) {
                int r = i >> 4, d4 = (i & 15) << 2, dp = (i & 15) << 1;
                size_t base = ((size_t)(b * Sq + kt * 64 + r)) * Dq + h * HD + d4;
                float4 kv = *(const float4*)&g_K[base];
                __half h0 = __float2half_rn(kv.x), h1 = __float2half_rn(kv.y);
                __half h2 = __float2half_rn(kv.z), h3 = __float2half_rn(kv.w);
                Kh[dp * 72 + r]       = pack_h2(h0, h1);
                Kh[(dp + 1) * 72 + r] = pack_h2(h2, h3);
                if (SPLIT) {
                    Kl[dp * 72 + r]       = pack_f2h(kv.x - __half2float(h0), kv.y - __half2float(h1));
                    Kl[(dp + 1) * 72 + r] = pack_f2h(kv.z - __half2float(h2), kv.w - __half2float(h3));
                }
            }
            float4 vr0[2], vr1[2];
#pragma unroll
            for (int ii = 0; ii < 2; ii++) {
                int i = tid + ii * 256;
                int kp = i >> 4, d4 = (i & 15) << 2;
                size_t base0 = ((size_t)(b * Sq + kt * 64 + 2 * kp)) * Dq + h * HD + d4;
                vr0[ii] = *(const float4*)&g_V[base0];
                vr1[ii] = *(const float4*)&g_V[base0 + Dq];
            }
            __syncthreads();

            float s[8][4];
#pragma unroll
            for (int nt = 0; nt < 8; nt++)
#pragma unroll
                for (int c = 0; c < 4; c++) s[nt][c] = 0.f;

#pragma unroll
            for (int ks = 0; ks < 4; ks++) {
                int kp0 = 8 * ks + tig, kp1 = 8 * ks + tig + 4;
                uint32_t a[4], al[4];
                a[0] = Qh[kp0 * 136 + mrow];
                a[1] = Qh[kp0 * 136 + mrow + 8];
                a[2] = Qh[kp1 * 136 + mrow];
                a[3] = Qh[kp1 * 136 + mrow + 8];
                if (SPLIT) {
                    al[0] = Ql[kp0 * 136 + mrow];
                    al[1] = Ql[kp0 * 136 + mrow + 8];
                    al[2] = Ql[kp1 * 136 + mrow];
                    al[3] = Ql[kp1 * 136 + mrow + 8];
                }
#pragma unroll
                for (int gq = 0; gq < 2; gq++) {
                    uint32_t bb[4][2], bl[4][2];
#pragma unroll
                    for (int j = 0; j < 4; j++) {
                        if (kt * 64 + (gq * 4 + j) * 8 > rowmax) continue;  // fully masked
                        int n0 = (gq * 4 + j) * 8 + gid;
                        bb[j][0] = Kh[kp0 * 72 + n0];
                        bb[j][1] = Kh[kp1 * 72 + n0];
                        if (SPLIT) {
                            bl[j][0] = Kl[kp0 * 72 + n0];
                            bl[j][1] = Kl[kp1 * 72 + n0];
                        }
                    }
#pragma unroll
                    for (int j = 0; j < 4; j++)
                        if (kt * 64 + (gq * 4 + j) * 8 <= rowmax)
                            mma_f16(s[gq * 4 + j], a, bb[j]);
                    if (SPLIT) {
#pragma unroll
                        for (int j = 0; j < 4; j++)
                            if (kt * 64 + (gq * 4 + j) * 8 <= rowmax)
                                mma_f16(s[gq * 4 + j], a, bl[j]);
#pragma unroll
                        for (int j = 0; j < 4; j++)
                            if (kt * 64 + (gq * 4 + j) * 8 <= rowmax)
                                mma_f16(s[gq * 4 + j], al, bb[j]);
                    }
                }
            }

            int rowg = qb * 128 + warp * 16 + gid;
            if (kt * 64 + 63 > rowg) {
#pragma unroll
                for (int nt = 0; nt < 8; nt++)
#pragma unroll
                    for (int c = 0; c < 4; c++) {
                        int col = kt * 64 + nt * 8 + 2 * tig + (c & 1);
                        int row = rowg + ((c & 2) ? 8 : 0);
                        float sv = s[nt][c] * 0.125f;
                        s[nt][c] = (col > row) ? -1e30f : sv;
                    }
            } else {
#pragma unroll
                for (int nt = 0; nt < 8; nt++)
#pragma unroll
                    for (int c = 0; c < 4; c++) s[nt][c] *= 0.125f;
            }

            float rmA = -1e30f, rmB = -1e30f;
#pragma unroll
            for (int nt = 0; nt < 8; nt++) {
                rmA = fmaxf(rmA, fmaxf(s[nt][0], s[nt][1]));
                rmB = fmaxf(rmB, fmaxf(s[nt][2], s[nt][3]));
            }
#pragma unroll
            for (int off = 1; off < 4; off <<= 1) {
                rmA = fmaxf(rmA, __shfl_xor_sync(0xffffffffu, rmA, off));
                rmB = fmaxf(rmB, __shfl_xor_sync(0xffffffffu, rmB, off));
            }
            float mnA = fmaxf(mA, rmA), mnB = fmaxf(mB, rmB);
            float alA = __expf(mA - mnA), alB = __expf(mB - mnB);
            float rsA = 0.f, rsB = 0.f;
#pragma unroll
            for (int nt = 0; nt < 8; nt++) {
                s[nt][0] = __expf(s[nt][0] - mnA); rsA += s[nt][0];
                s[nt][1] = __expf(s[nt][1] - mnA); rsA += s[nt][1];
                s[nt][2] = __expf(s[nt][2] - mnB); rsB += s[nt][2];
                s[nt][3] = __expf(s[nt][3] - mnB); rsB += s[nt][3];
            }
#pragma unroll
            for (int off = 1; off < 4; off <<= 1) {
                rsA += __shfl_xor_sync(0xffffffffu, rsA, off);
                rsB += __shfl_xor_sync(0xffffffffu, rsB, off);
            }
            lA = lA * alA + rsA; mA = mnA;
            lB = lB * alB + rsB; mB = mnB;
#pragma unroll
            for (int nt = 0; nt < 8; nt++) {
                o[nt][0] *= alA; o[nt][1] *= alA;
                o[nt][2] *= alB; o[nt][3] *= alB;
            }

#pragma unroll
            for (int nt = 0; nt < 8; nt++) {
                int kpP = nt * 4 + tig;
                __half p0 = __float2half_rn(s[nt][0]), p1 = __float2half_rn(s[nt][1]);
                __half p2 = __float2half_rn(s[nt][2]), p3 = __float2half_rn(s[nt][3]);
                Ph[kpP * 136 + mrow]     = pack_h2(p0, p1);
                Ph[kpP * 136 + mrow + 8] = pack_h2(p2, p3);
                if (SPLIT) {
                    Pl[kpP * 136 + mrow]     = pack_f2h(s[nt][0] - __half2float(p0),
                                                        s[nt][1] - __half2float(p1));
                    Pl[kpP * 136 + mrow + 8] = pack_f2h(s[nt][2] - __half2float(p2),
                                                        s[nt][3] - __half2float(p3));
                }
            }
#pragma unroll
            for (int ii = 0; ii < 2; ii++) {
                int i = tid + ii * 256;
                int kp = i >> 4, d4 = (i & 15) << 2;
                float a0[4] = {vr0[ii].x, vr0[ii].y, vr0[ii].z, vr0[ii].w};
                float a1[4] = {vr1[ii].x, vr1[ii].y, vr1[ii].z, vr1[ii].w};
#pragma unroll
                for (int j = 0; j < 4; j++) {
                    __half p0 = __float2half_rn(a0[j]), p1 = __float2half_rn(a1[j]);
                    Vh[kp * 72 + d4 + j] = pack_h2(p0, p1);
                    if (SPLIT)
                        Vl[kp * 72 + d4 + j] = pack_f2h(a0[j] - __half2float(p0),
                                                        a1[j] - __half2float(p1));
                }
            }
            __syncthreads();

#pragma unroll
            for (int ks = 0; ks < 4; ks++) {
                if (kt * 64 + 16 * ks > rowmax) continue;  // P entries exactly 0
                int kp0 = 8 * ks + tig, kp1 = 8 * ks + tig + 4;
                uint32_t a[4], al[4];
                a[0] = Ph[kp0 * 136 + mrow];
                a[1] = Ph[kp0 * 136 + mrow + 8];
                a[2] = Ph[kp1 * 136 + mrow];
                a[3] = Ph[kp1 * 136 + mrow + 8];
                if (SPLIT) {
                    al[0] = Pl[kp0 * 136 + mrow];
                    al[1] = Pl[kp0 * 136 + mrow + 8];
                    al[2] = Pl[kp1 * 136 + mrow];
                    al[3] = Pl[kp1 * 136 + mrow + 8];
                }
#pragma unroll
                for (int gq = 0; gq < 2; gq++) {
                    uint32_t bb[4][2], bl[4][2];
#pragma unroll
                    for (int j = 0; j < 4; j++) {
                        int n0 = (gq * 4 + j) * 8 + gid;
                        bb[j][0] = Vh[kp0 * 72 + n0];
                        bb[j][1] = Vh[kp1 * 72 + n0];
                        if (SPLIT) {
                            bl[j][0] = Vl[kp0 * 72 + n0];
                            bl[j][1] = Vl[kp1 * 72 + n0];
                        }
                    }
#pragma unroll
                    for (int j = 0; j < 4; j++) mma_f16(o[gq * 4 + j], a, bb[j]);
                    if (SPLIT) {
#pragma unroll
                        for (int j = 0; j < 4; j++) mma_f16(o[gq * 4 + j], a, bl[j]);
#pragma unroll
                        for (int j = 0; j < 4; j++) mma_f16(o[gq * 4 + j], al, bb[j]);
                    }
                }
            }
        }

        float invA = 1.0f / lA, invB = 1.0f / lB;
        size_t rbase0 = ((size_t)(b * Sq + qb * 128 + warp * 16 + gid)) * Dq + h * HD;
        size_t rbase1 = rbase0 + (size_t)8 * Dq;
#pragma unroll
        for (int nt = 0; nt < 8; nt++) {
            int d0 = nt * 8 + 2 * tig;
            *(float2*)&g_Y[rbase0 + d0] = make_float2(o[nt][0] * invA, o[nt][1] * invA);
            *(float2*)&g_Y[rbase1 + d0] = make_float2(o[nt][2] * invB, o[nt][3] * invB);
        }
        __syncthreads();
    }
}

// ---------------- fp16 1-pass flash (layer 1, pipelined, qb-paired) ----------
#define F0_Q  (32*136)
#define F0_K  (32*72)
#define F0_V  (32*72)
#define F0_P  (32*136)
#define FL0_SMEM ((F0_Q + F0_K + 2*F0_V + F0_P) * 4)   // 62464 B

__global__ void __launch_bounds__(256, 2)
flash_h0() {
    extern __shared__ uint32_t fu[];
    uint32_t* Qh = fu;
    uint32_t* Kh = Qh + F0_Q;
    uint32_t* Vh0 = Kh + F0_K;
    uint32_t* Vh1 = Vh0 + F0_V;
    uint32_t* Ph = Vh1 + F0_V;

    int h = blockIdx.y, b = blockIdx.z;
    int tid = threadIdx.x, warp = tid >> 5, lane = tid & 31;
    int gid = lane >> 2, tig = lane & 3;
    int mrow = warp * 16 + gid;

    for (int hf = 0; hf < 2; hf++) {
        int qb = (hf == 0) ? (7 - (int)blockIdx.x) : (int)blockIdx.x;
        int rowmax = qb * 128 + warp * 16 + 15;
        if (hf) __syncthreads();

        for (int i = tid; i < 1024; i += 256) {
            int r = i >> 3, d8 = (i & 7) << 3, dp = d8 >> 1;
            uint4 u = *(const uint4*)&g_Qh[((size_t)(b * Sq + qb * 128 + r)) * Dq + h * HD + d8];
            Qh[(dp + 0) * 136 + r] = u.x;
            Qh[(dp + 1) * 136 + r] = u.y;
            Qh[(dp + 2) * 136 + r] = u.z;
            Qh[(dp + 3) * 136 + r] = u.w;
        }
        for (int i = tid; i < 512; i += 256) {
            int r = i >> 3, d8 = (i & 7) << 3, dp = d8 >> 1;
            uint4 u = *(const uint4*)&g_Kh[((size_t)(b * Sq + r)) * Dq + h * HD + d8];
            Kh[(dp + 0) * 72 + r] = u.x;
            Kh[(dp + 1) * 72 + r] = u.y;
            Kh[(dp + 2) * 72 + r] = u.z;
            Kh[(dp + 3) * 72 + r] = u.w;
        }
        for (int i = tid; i < 512; i += 256) {
            int kp = i >> 4, d4 = (i & 15) << 2;
            size_t base0 = ((size_t)(b * Sq + 2 * kp)) * Dq + h * HD + d4;
            uint2 a = *(const uint2*)&g_Vh[base0];
            uint2 c = *(const uint2*)&g_Vh[base0 + Dq];
            Vh0[kp * 72 + d4 + 0] = __byte_perm(a.x, c.x, 0x5410);
            Vh0[kp * 72 + d4 + 1] = __byte_perm(a.x, c.x, 0x7632);
            Vh0[kp * 72 + d4 + 2] = __byte_perm(a.y, c.y, 0x5410);
            Vh0[kp * 72 + d4 + 3] = __byte_perm(a.y, c.y, 0x7632);
        }
        __syncthreads();

        float mA = -1e30f, mB = -1e30f, lA = 0.f, lB = 0.f;
        float o[8][4];
#pragma unroll
        for (int nt = 0; nt < 8; nt++)
#pragma unroll
            for (int c = 0; c < 4; c++) o[nt][c] = 0.f;

        int nkt = 2 * qb + 2;
        for (int kt = 0; kt < nkt; kt++) {
            uint32_t* Vcur = (kt & 1) ? Vh1 : Vh0;
            uint32_t* Vnxt = (kt & 1) ? Vh0 : Vh1;

            uint4 kreg[2];
            uint2 va[2], vb[2];
            bool more = (kt + 1 < nkt);
            if (more) {
#pragma unroll
                for (int ii = 0; ii < 2; ii++) {
                    int i = tid + ii * 256;
                    int r = i >> 3, d8 = (i & 7) << 3;
                    kreg[ii] = *(const uint4*)&g_Kh[((size_t)(b * Sq + (kt + 1) * 64 + r)) * Dq + h * HD + d8];
                }
#pragma unroll
                for (int ii = 0; ii < 2; ii++) {
                    int i = tid + ii * 256;
                    int kp = i >> 4, d4 = (i & 15) << 2;
                    size_t base0 = ((size_t)(b * Sq + (kt + 1) * 64 + 2 * kp)) * Dq + h * HD + d4;
                    va[ii] = *(const uint2*)&g_Vh[base0];
                    vb[ii] = *(const uint2*)&g_Vh[base0 + Dq];
                }
            }

            float s[8][4];
#pragma unroll
            for (int nt = 0; nt < 8; nt++)
#pragma unroll
                for (int c = 0; c < 4; c++) s[nt][c] = 0.f;
#pragma unroll
            for (int ks = 0; ks < 4; ks++) {
                int kp0 = 8 * ks + tig, kp1 = 8 * ks + tig + 4;
                uint32_t a[4];
                a[0] = Qh[kp0 * 136 + mrow];
                a[1] = Qh[kp0 * 136 + mrow + 8];
                a[2] = Qh[kp1 * 136 + mrow];
                a[3] = Qh[kp1 * 136 + mrow + 8];
#pragma unroll
                for (int gq = 0; gq < 2; gq++) {
                    uint32_t bb[4][2];
#pragma unroll
                    for (int j = 0; j < 4; j++) {
                        if (kt * 64 + (gq * 4 + j) * 8 > rowmax) continue;
                        int n0 = (gq * 4 + j) * 8 + gid;
                        bb[j][0] = Kh[kp0 * 72 + n0];
                        bb[j][1] = Kh[kp1 * 72 + n0];
                    }
#pragma unroll
                    for (int j = 0; j < 4; j++)
                        if (kt * 64 + (gq * 4 + j) * 8 <= rowmax)
                            mma_f16(s[gq * 4 + j], a, bb[j]);
                }
            }

            int rowg = qb * 128 + warp * 16 + gid;
            if (kt * 64 + 63 > rowg) {
#pragma unroll
                for (int nt = 0; nt < 8; nt++)
#pragma unroll
                    for (int c = 0; c < 4; c++) {
                        int col = kt * 64 + nt * 8 + 2 * tig + (c & 1);
                        int row = rowg + ((c & 2) ? 8 : 0);
                        float sv = s[nt][c] * 0.125f;
                        s[nt][c] = (col > row) ? -1e30f : sv;
                    }
            } else {
#pragma unroll
                for (int nt = 0; nt < 8; nt++)
#pragma unroll
                    for (int c = 0; c < 4; c++) s[nt][c] *= 0.125f;
            }

            float rmA = -1e30f, rmB = -1e30f;
#pragma unroll
            for (int nt = 0; nt < 8; nt++) {
                rmA = fmaxf(rmA, fmaxf(s[nt][0], s[nt][1]));
                rmB = fmaxf(rmB, fmaxf(s[nt][2], s[nt][3]));
            }
#pragma unroll
            for (int off = 1; off < 4; off <<= 1) {
                rmA = fmaxf(rmA, __shfl_xor_sync(0xffffffffu, rmA, off));
                rmB = fmaxf(rmB, __shfl_xor_sync(0xffffffffu, rmB, off));
            }
            float mnA = fmaxf(mA, rmA), mnB = fmaxf(mB, rmB);
            float alA = __expf(mA - mnA), alB = __expf(mB - mnB);
            float rsA = 0.f, rsB = 0.f;
#pragma unroll
            for (int nt = 0; nt < 8; nt++) {
                s[nt][0] = __expf(s[nt][0] - mnA); rsA += s[nt][0];
                s[nt][1] = __expf(s[nt][1] - mnA); rsA += s[nt][1];
                s[nt][2] = __expf(s[nt][2] - mnB); rsB += s[nt][2];
                s[nt][3] = __expf(s[nt][3] - mnB); rsB += s[nt][3];
            }
#pragma unroll
            for (int off = 1; off < 4; off <<= 1) {
                rsA += __shfl_xor_sync(0xffffffffu, rsA, off);
                rsB += __shfl_xor_sync(0xffffffffu, rsB, off);
            }
            lA = lA * alA + rsA; mA = mnA;
            lB = lB * alB + rsB; mB = mnB;
#pragma unroll
            for (int nt = 0; nt < 8; nt++) {
                o[nt][0] *= alA; o[nt][1] *= alA;
                o[nt][2] *= alB; o[nt][3] *= alB;
            }

            __syncthreads();

#pragma unroll
            for (int nt = 0; nt < 8; nt++) {
                int kpP = nt * 4 + tig;
                Ph[kpP * 136 + mrow]     = pack_f2h(s[nt][0], s[nt][1]);
                Ph[kpP * 136 + mrow + 8] = pack_f2h(s[nt][2], s[nt][3]);
            }
            if (more) {
#pragma unroll
                for (int ii = 0; ii < 2; ii++) {
                    int i = tid + ii * 256;
                    int r = i >> 3, dp = ((i & 7) << 3) >> 1;
                    Kh[(dp + 0) * 72 + r] = kreg[ii].x;
                    Kh[(dp + 1) * 72 + r] = kreg[ii].y;
                    Kh[(dp + 2) * 72 + r] = kreg[ii].z;
                    Kh[(dp + 3) * 72 + r] = kreg[ii].w;
                }
#pragma unroll
                for (int ii = 0; ii < 2; ii++) {
                    int i = tid + ii * 256;
                    int kp = i >> 4, d4 = (i & 15) << 2;
                    Vnxt[kp * 72 + d4 + 0] = __byte_perm(va[ii].x, vb[ii].x, 0x5410);
                    Vnxt[kp * 72 + d4 + 1] = __byte_perm(va[ii].x, vb[ii].x, 0x7632);
                    Vnxt[kp * 72 + d4 + 2] = __byte_perm(va[ii].y, vb[ii].y, 0x5410);
                    Vnxt[kp * 72 + d4 + 3] = __byte_perm(va[ii].y, vb[ii].y, 0x7632);
                }
            }
            __syncthreads();

#pragma unroll
            for (int ks = 0; ks < 4; ks++) {
                if (kt * 64 + 16 * ks > rowmax) continue;
                int kp0 = 8 * ks + tig, kp1 = 8 * ks + tig + 4;
                uint32_t a[4];
                a[0] = Ph[kp0 * 136 + mrow];
                a[1] = Ph[kp0 * 136 + mrow + 8];
                a[2] = Ph[kp1 * 136 + mrow];
                a[3] = Ph[kp1 * 136 + mrow + 8];
#pragma unroll
                for (int gq = 0; gq < 2; gq++) {
                    uint32_t bb[4][2];
#pragma unroll
                    for (int j = 0; j < 4; j++) {
                        int n0 = (gq * 4 + j) * 8 + gid;
                        bb[j][0] = Vcur[kp0 * 72 + n0];
                        bb[j][1] = Vcur[kp1 * 72 + n0];
                    }
#pragma unroll
                    for (int j = 0; j < 4; j++) mma_f16(o[gq * 4 + j], a, bb[j]);
                }
            }
        }

        float invA = 1.0f / lA, invB = 1.0f / lB;
        size_t rbase0 = ((size_t)(b * Sq + qb * 128 + warp * 16 + gid)) * Dq + h * HD;
        size_t rbase1 = rbase0 + (size_t)8 * Dq;
#pragma unroll
        for (int nt = 0; nt < 8; nt++) {
            int d0 = nt * 8 + 2 * tig;
            *(uint32_t*)&g_Yh[rbase0 + d0] = pack_f2h(o[nt][0] * invA, o[nt][1] * invA);
            *(uint32_t*)&g_Yh[rbase1 + d0] = pack_f2h(o[nt][2] * invB, o[nt][3] * invB);
        }
    }
}

// ---------------- gating -----------------------------------------------------
// token mode: top-2 + assignment fused (counts zeroed by preceding ln kernel)
__global__ void gate_token_kernel(const float* __restrict__ gw,
                                  const float* __restrict__ gb, int layer) {
    int t = blockIdx.x * 4 + (threadIdx.x >> 5);
    int lane = threadIdx.x & 31;
    if (t >= TOK) return;
    const float* hrow = g_H + (size_t)t * Dq;
    const float* gwl = gw + (size_t)layer * Dq * Ee;
    float acc[Ee] = {};
    for (int d = lane; d < Dq; d += 32) {
        float hv = hrow[d];
        const float* g = gwl + (size_t)d * Ee;
#pragma unroll
        for (int e = 0; e < Ee; e++) acc[e] += hv * g[e];
    }
#pragma unroll
    for (int e = 0; e < Ee; e++)
        for (int off = 16; off; off >>= 1)
            acc[e] += __shfl_xor_sync(0xffffffffu, acc[e], off);
    if (lane == 0) {
        float lg[Ee];
#pragma unroll
        for (int e = 0; e < Ee; e++) lg[e] = acc[e] + gb[layer * Ee + e];
        int i1, i2; float w1, w2;
        top2_of8(lg, i1, i2, w1, w2);
        int s1 = atomicAdd(&g_counts[i1], 1);
        g_tok[i1 * TOK + s1] = t; g_wt[i1 * TOK + s1] = w1;
        g_islot[t * 2] = i1 * TOK + s1;
        int s2 = atomicAdd(&g_counts[i2], 1);
        g_tok[i2 * TOK + s2] = t; g_wt[i2 * TOK + s2] = w2;
        g_islot[t * 2 + 1] = i2 * TOK + s2;
    }
}

__global__ void xmean_kernel() {
    int b = blockIdx.y;
    int d = blockIdx.x * 256 + threadIdx.x;
    float s = 0.f;
    for (int ss = 0; ss < Sq; ss++)
        s += g_H[((size_t)(b * Sq + ss)) * Dq + d];
    g_xmean[b * Dq + d] = s * (1.0f / Sq);
}

__global__ void gate_seq_kernel(const float* __restrict__ gw,
                                const float* __restrict__ gb, int layer) {
    if (blockIdx.x == 0 && threadIdx.x < Ee) g_counts[threadIdx.x] = 0;
    int b = blockIdx.x;
    int tid = threadIdx.x, e = tid >> 5, lane = tid & 31;
    const float* gwl = gw + (size_t)layer * Dq * Ee;
    float acc = 0.f;
    for (int d = lane; d < Dq; d += 32)
        acc += g_xmean[b * Dq + d] * gwl[(size_t)d * Ee + e];
    for (int off = 16; off; off >>= 1)
        acc += __shfl_xor_sync(0xffffffffu, acc, off);
    __shared__ float lg[Ee];
    if (lane == 0) lg[e] = acc + gb[layer * Ee + e];
    __syncthreads();
    if (tid == 0) {
        int i1, i2; float w1, w2;
        top2_of8(lg, i1, i2, w1, w2);
        g_bsel[b * 2] = i1; g_bsel[b * 2 + 1] = i2;
        g_bw[b * 2] = w1;  g_bw[b * 2 + 1] = w2;
    }
}

__global__ void assign_seq_kernel() {
    int t = blockIdx.x * 256 + threadIdx.x;
    if (t >= TOK) return;
    int b = t / Sq;
    int e1 = g_bsel[b * 2], e2 = g_bsel[b * 2 + 1];
    float w1 = g_bw[b * 2], w2 = g_bw[b * 2 + 1];
    int s1 = atomicAdd(&g_counts[e1], 1);
    g_tok[e1 * TOK + s1] = t; g_wt[e1 * TOK + s1] = w1;
    g_islot[t * 2] = e1 * TOK + s1;
    int s2 = atomicAdd(&g_counts[e2], 1);
    g_tok[e2 * TOK + s2] = t; g_wt[e2 * TOK + s2] = w2;
    g_islot[t * 2 + 1] = e2 * TOK + s2;
}

// ---------------- host side --------------------------------------------------
extern "C" void kernel_launch(void* const* d_in, const int* in_sizes, int n_in,
                              void* d_out, int out_size) {
    const float* x      = (const float*)d_in[0];
    const float* ln1_w  = (const float*)d_in[1];
    const float* ln1_b  = (const float*)d_in[2];
    const float* ln2_w  = (const float*)d_in[3];
    const float* ln2_b  = (const float*)d_in[4];
    const float* wq     = (const float*)d_in[5];
    const float* wk     = (const float*)d_in[6];
    const float* wv     = (const float*)d_in[7];
    const float* wo     = (const float*)d_in[8];
    const float* bq     = (const float*)d_in[9];
    const float* bk     = (const float*)d_in[10];
    const float* bv     = (const float*)d_in[11];
    const float* bo     = (const float*)d_in[12];
    const float* gate_w = (const float*)d_in[13];
    const float* gate_b = (const float*)d_in[14];
    const float* e_w1   = (const float*)d_in[15];
    const float* e_b1   = (const float*)d_in[16];
    const float* e_w2   = (const float*)d_in[17];
    const float* e_b2   = (const float*)d_in[18];

    float *Xp, *Hp, *Qp, *Kp, *Vp, *Yp;
    void *Qhp, *Khp, *Vhp, *Yhp;
    cudaGetSymbolAddress((void**)&Xp, g_X);
    cudaGetSymbolAddress((void**)&Hp, g_H);
    cudaGetSymbolAddress((void**)&Qp, g_Q);
    cudaGetSymbolAddress((void**)&Kp, g_K);
    cudaGetSymbolAddress((void**)&Vp, g_V);
    cudaGetSymbolAddress((void**)&Yp, g_Y);
    cudaGetSymbolAddress(&Qhp, g_Qh);
    cudaGetSymbolAddress(&Khp, g_Kh);
    cudaGetSymbolAddress(&Vhp, g_Vh);
    cudaGetSymbolAddress(&Yhp, g_Yh);

    static int attr_set = 0;
    if (!attr_set) {
        cudaFuncSetAttribute(gemm_h3<0>, cudaFuncAttributeMaxDynamicSharedMemorySize, SMEM_H3);
        cudaFuncSetAttribute(gemm_h3<1>, cudaFuncAttributeMaxDynamicSharedMemorySize, SMEM_H3);
        cudaFuncSetAttribute(gemm_hb<0>, cudaFuncAttributeMaxDynamicSharedMemorySize, SMEM_HB);
        cudaFuncSetAttribute(gemm_hb<1>, cudaFuncAttributeMaxDynamicSharedMemorySize, SMEM_HB);
        cudaFuncSetAttribute(gemm_hb<2>, cudaFuncAttributeMaxDynamicSharedMemorySize, SMEM_HB);
        cudaFuncSetAttribute(gemm_hb<3>, cudaFuncAttributeMaxDynamicSharedMemorySize, SMEM_HB);
        cudaFuncSetAttribute(flash_h<1>, cudaFuncAttributeMaxDynamicSharedMemorySize, FL2_SMEM1);
        cudaFuncSetAttribute(flash_h0,   cudaFuncAttributeMaxDynamicSharedMemorySize, FL0_SMEM);
        attr_set = 1;
    }

    const size_t DD = (size_t)Dq * Dq;
    const int nelem = TOK * Dq;

    copy_in_kernel<<<nelem / 256, 256>>>(x);

    for (int l = 0; l < Ll; l++) {
        const float* WQ = wq + l * DD;
        const float* WK = wk + l * DD;
        const float* WV = wv + l * DD;
        const float* WO = wo + l * DD;
        const float* BQ = bq + (size_t)l * Dq;
        const float* BK = bk + (size_t)l * Dq;
        const float* BV = bv + (size_t)l * Dq;
        const float* BO = bo + (size_t)l * Dq;

        if (l == 0)
            ln_kernel_t<0><<<TOK, 256>>>(ln1_w + (size_t)l * Dq, ln1_b + (size_t)l * Dq);
        else
            ln_combine_kernel<<<TOK, 256>>>(ln1_w + (size_t)l * Dq, ln1_b + (size_t)l * Dq);

        if (l == 0) {
            gemm_h3<0><<<dim3(8, 32, 3), 512, SMEM_H3>>>(
                Hp, WQ, WK, WV, BQ, BK, BV, Qp, Kp, Vp, Dq, Dq);
            flash_h<1><<<dim3(4, Hh, Bq), 256, FL2_SMEM1>>>();
            gemm_h3<1><<<dim3(8, 32), 512, SMEM_H3>>>(
                Yp, WO, nullptr, nullptr, BO, nullptr, nullptr, Xp, nullptr, nullptr, Dq, Dq);
        } else {
            gemm_hb<0><<<dim3(4, 32, 3), 512, SMEM_HB>>>(
                Hp, WQ, WK, WV, BQ, BK, BV, Qhp, Khp, Vhp, Dq, Dq, l);
            flash_h0<<<dim3(4, Hh, Bq), 256, FL0_SMEM>>>();
            gemm_hb<1><<<dim3(4, 32), 512, SMEM_HB>>>(
                Yhp, WO, nullptr, nullptr, BO, nullptr, nullptr, Xp, nullptr, nullptr, Dq, Dq, l);
        }

        // ln2 zeroes MoE counts (consumed by the gate/assign launches that follow)
        ln_kernel_t<1><<<TOK, 256>>>(ln2_w + (size_t)l * Dq, ln2_b + (size_t)l * Dq);
        if (l % 2 == 0) {
            gate_token_kernel<<<TOK / 4, 128>>>(gate_w, gate_b, l);   // fused assign
        } else {
            xmean_kernel<<<dim3(Dq / 256, Bq), 256>>>();
            gate_seq_kernel<<<Bq, 256>>>(gate_w, gate_b, l);
            assign_seq_kernel<<<TOK / 256, 256>>>();
        }
        gemm_hb<2><<<dim3(DFFq / 256, TOK / 128, Ee), 512, SMEM_HB>>>(
            nullptr, e_w1, nullptr, nullptr, e_b1, nullptr, nullptr,
            nullptr, nullptr, nullptr, Dq, DFFq, l);
        gemm_hb<3><<<dim3(Dq / 256, TOK / 128, Ee), 512, SMEM_HB>>>(
            nullptr, e_w2, nullptr, nullptr, e_b2, nullptr, nullptr,
            nullptr, nullptr, nullptr, DFFq, Dq, l);
    }

    combine_out_kernel<<<nelem / 1024, 256>>>((float*)d_out);
    (void)in_sizes; (void)n_in; (void)out_size;
}

// round 17
// speedup vs baseline: 1.0079x; 1.0079x over previous
#include <cuda_runtime.h>
#include <cuda_fp16.h>
#include <math.h>
#include <stdint.h>

#define Bq   4
#define Sq   1024
#define Dq   1024
#define Hh   16
#define HD   64
#define Ll   2
#define Ee   8
#define DFFq 4096
#define TOK  (Bq*Sq)   // 4096

// ---------------- static scratch ---------------------------------------------
__device__ float g_X[TOK*Dq];
__device__ float g_H[TOK*Dq];
__device__ float g_Q[TOK*Dq];          // layer-0 (fp32, split path)
__device__ float g_K[TOK*Dq];
__device__ float g_V[TOK*Dq];
__device__ float g_Y[TOK*Dq];
__device__ __half g_Qh[TOK*Dq];        // layer-1 (fp16 path)
__device__ __half g_Kh[TOK*Dq];
__device__ __half g_Vh[TOK*Dq];
__device__ __half g_Yh[TOK*Dq];
__device__ __half g_hidden_h[(size_t)Ee*TOK*DFFq];   // 256MB fp16
__device__ float g_moeout[(size_t)Ee*TOK*Dq];
__device__ int   g_counts[Ee];
__device__ int   g_tok[Ee*TOK];
__device__ float g_wt[Ee*TOK];
__device__ int   g_islot[TOK*2];
__device__ int   g_bsel[Bq*2];
__device__ float g_bw[Bq*2];
__device__ float g_xmean[Bq*Dq];

// ---------------- helpers ----------------------------------------------------
__device__ __forceinline__ void top2_of8(const float* lg, int& i1, int& i2,
                                         float& w1, float& w2) {
    i1 = 0; float v1 = lg[0];
#pragma unroll
    for (int e = 1; e < Ee; e++) if (lg[e] > v1) { v1 = lg[e]; i1 = e; }
    i2 = -1; float v2 = -3.0e38f;
#pragma unroll
    for (int e = 0; e < Ee; e++) if (e != i1 && lg[e] > v2) { v2 = lg[e]; i2 = e; }
    float ex = expf(v2 - v1);
    w1 = 1.0f / (1.0f + ex);
    w2 = ex / (1.0f + ex);
}
__device__ __forceinline__ float gelu_exact(float x) {
    return 0.5f * x * (1.0f + erff(x * 0.7071067811865476f));
}
__device__ __forceinline__ void mma_f16(float c[4], const uint32_t a[4],
                                        const uint32_t b[2]) {
    asm volatile(
        "mma.sync.aligned.m16n8k16.row.col.f32.f16.f16.f32 "
        "{%0,%1,%2,%3},{%4,%5,%6,%7},{%8,%9},{%0,%1,%2,%3};"
        : "+f"(c[0]), "+f"(c[1]), "+f"(c[2]), "+f"(c[3])
        : "r"(a[0]), "r"(a[1]), "r"(a[2]), "r"(a[3]), "r"(b[0]), "r"(b[1]));
}
__device__ __forceinline__ uint32_t pack_h2(__half a, __half b) {
    __half2 h = __halves2half2(a, b);
    return *(uint32_t*)&h;
}
__device__ __forceinline__ uint32_t pack_f2h(float a, float b) {
    return pack_h2(__float2half_rn(a), __float2half_rn(b));
}

// ---------------- simple kernels ---------------------------------------------
// fused copy_in + ln1 (layer 0): reads input directly, writes g_X and g_H
__global__ void ln_in_kernel(const float* __restrict__ src,
                             const float* __restrict__ w, const float* __restrict__ b) {
    int t = blockIdx.x, tid = threadIdx.x;
    const float* xr = src + (size_t)t * Dq;
    float* xo = g_X + (size_t)t * Dq;
    float s = 0.f, s2 = 0.f;
    for (int d = tid; d < Dq; d += 256) {
        float v = xr[d];
        xo[d] = v;
        s += v; s2 += v * v;
    }
    __shared__ float r1[256], r2[256];
    r1[tid] = s; r2[tid] = s2; __syncthreads();
    for (int off = 128; off; off >>= 1) {
        if (tid < off) { r1[tid] += r1[tid + off]; r2[tid] += r2[tid + off]; }
        __syncthreads();
    }
    float mean = r1[0] * (1.0f / Dq);
    float var  = r2[0] * (1.0f / Dq) - mean * mean;
    float rstd = rsqrtf(var + 1e-5f);
    float* hr = g_H + (size_t)t * Dq;
    for (int d = tid; d < Dq; d += 256)
        hr[d] = (xr[d] - mean) * rstd * w[d] + b[d];
}

// ln2 variant zeroes MoE counts (consumed by the NEXT launch, gate/assign)
template<int ZERO_CNT>
__global__ void ln_kernel_t(const float* __restrict__ w, const float* __restrict__ b) {
    if (ZERO_CNT && blockIdx.x == 0 && threadIdx.x < Ee) g_counts[threadIdx.x] = 0;
    int t = blockIdx.x, tid = threadIdx.x;
    const float* xr = g_X + (size_t)t * Dq;
    float s = 0.f, s2 = 0.f;
    for (int d = tid; d < Dq; d += 256) { float v = xr[d]; s += v; s2 += v * v; }
    __shared__ float r1[256], r2[256];
    r1[tid] = s; r2[tid] = s2; __syncthreads();
    for (int off = 128; off; off >>= 1) {
        if (tid < off) { r1[tid] += r1[tid + off]; r2[tid] += r2[tid + off]; }
        __syncthreads();
    }
    float mean = r1[0] * (1.0f / Dq);
    float var  = r2[0] * (1.0f / Dq) - mean * mean;
    float rstd = rsqrtf(var + 1e-5f);
    float* hr = g_H + (size_t)t * Dq;
    for (int d = tid; d < Dq; d += 256)
        hr[d] = (xr[d] - mean) * rstd * w[d] + b[d];
}

__global__ void ln_combine_kernel(const float* __restrict__ w, const float* __restrict__ b) {
    int t = blockIdx.x, tid = threadIdx.x;
    int s0 = g_islot[t * 2], s1 = g_islot[t * 2 + 1];
    float* xr = g_X + (size_t)t * Dq;
    const float* m0 = g_moeout + (size_t)s0 * Dq;
    const float* m1 = g_moeout + (size_t)s1 * Dq;
    float s = 0.f, s2 = 0.f;
    for (int d = tid; d < Dq; d += 256) {
        float v = xr[d] + m0[d] + m1[d];
        xr[d] = v;
        s += v; s2 += v * v;
    }
    __shared__ float r1[256], r2[256];
    r1[tid] = s; r2[tid] = s2; __syncthreads();
    for (int off = 128; off; off >>= 1) {
        if (tid < off) { r1[tid] += r1[tid + off]; r2[tid] += r2[tid + off]; }
        __syncthreads();
    }
    float mean = r1[0] * (1.0f / Dq);
    float var  = r2[0] * (1.0f / Dq) - mean * mean;
    float rstd = rsqrtf(var + 1e-5f);
    float* hr = g_H + (size_t)t * Dq;
    for (int d = tid; d < Dq; d += 256)
        hr[d] = (xr[d] - mean) * rstd * w[d] + b[d];
}

__global__ void combine_out_kernel(float* __restrict__ dst) {
    int i = blockIdx.x * 256 + threadIdx.x;
    int t = i >> 8;
    int c4 = (i & 255) << 2;
    int s0 = g_islot[t * 2], s1 = g_islot[t * 2 + 1];
    float4 a = *(const float4*)&g_moeout[(size_t)s0 * Dq + c4];
    float4 b = *(const float4*)&g_moeout[(size_t)s1 * Dq + c4];
    float4 x = *(const float4*)&g_X[(size_t)t * Dq + c4];
    x.x += a.x + b.x; x.y += a.y + b.y; x.z += a.z + b.z; x.w += a.w + b.w;
    *(float4*)&dst[(size_t)t * Dq + c4] = x;
}

// ---------------- fp16 3-pass split GEMM (layer-0, 128x128, BK=32) -----------
#define T2W 136
#define T2SZ (16*T2W)
#define H3BUF (4*T2SZ)
#define SMEM_H3 (2*H3BUF*4)           // 69632 B

template<int MODE>
__global__ void __launch_bounds__(512, 1)
gemm_h3(const float* __restrict__ A,
        const float* __restrict__ W0, const float* __restrict__ W1,
        const float* __restrict__ W2,
        const float* __restrict__ b0, const float* __restrict__ b1,
        const float* __restrict__ b2,
        float* __restrict__ C0, float* __restrict__ C1, float* __restrict__ C2,
        int Kd, int N) {
    extern __shared__ uint32_t tiles[];
    int z = (MODE == 0) ? blockIdx.z : 0;
    const float* Wall = (z == 0) ? W0 : (z == 1 ? W1 : W2);
    const float* bias = (z == 0) ? b0 : (z == 1 ? b1 : b2);
    float* Cp         = (z == 0) ? C0 : (z == 1 ? C1 : C2);

    int tid = threadIdx.x;
    int rowBase = blockIdx.y * 128, colBase = blockIdx.x * 128;

    int lrA = tid >> 2, kcA4 = (tid & 3) << 2, kpA = (tid & 3) << 1;
    const float* Ap = A + (size_t)(rowBase + lrA) * Kd + kcA4;
    int kpB = tid >> 6, nB = (tid & 63) << 1;
    const float* Wp = Wall + (size_t)(2 * kpB) * N + colBase + nB;

    int lane = tid & 31, warp = tid >> 5;
    int wm = (warp & 3) * 32, wn = (warp >> 2) * 32;
    int gid = lane >> 2, tig = lane & 3;

    float acc[2][4][4];
#pragma unroll
    for (int a = 0; a < 2; a++)
#pragma unroll
        for (int b3 = 0; b3 < 4; b3++)
#pragma unroll
            for (int c = 0; c < 4; c++) acc[a][b3][c] = 0.f;

    int nk = Kd / 32;
    float4 av0, av1;
    float2 br0, br1, br2, br3;
    av0 = *(const float4*)(Ap);
    av1 = *(const float4*)(Ap + 16);
    br0 = *(const float2*)(Wp);
    br1 = *(const float2*)(Wp + N);
    br2 = *(const float2*)(Wp + (size_t)16 * N);
    br3 = *(const float2*)(Wp + (size_t)17 * N);

#define H3_STORE(BUF)                                                          \
    {                                                                          \
        uint32_t* Ahi = (BUF);                                                 \
        uint32_t* Alo = (BUF) + T2SZ;                                          \
        uint32_t* Bhi = (BUF) + 2 * T2SZ;                                      \
        uint32_t* Blo = (BUF) + 3 * T2SZ;                                      \
        __half h0 = __float2half_rn(av0.x), h1 = __float2half_rn(av0.y);       \
        __half h2 = __float2half_rn(av0.z), h3 = __float2half_rn(av0.w);       \
        Ahi[kpA * T2W + lrA]       = pack_h2(h0, h1);                          \
        Ahi[(kpA + 1) * T2W + lrA] = pack_h2(h2, h3);                          \
        Alo[kpA * T2W + lrA]       = pack_f2h(av0.x - __half2float(h0), av0.y - __half2float(h1)); \
        Alo[(kpA + 1) * T2W + lrA] = pack_f2h(av0.z - __half2float(h2), av0.w - __half2float(h3)); \
        __half g0 = __float2half_rn(av1.x), g1 = __float2half_rn(av1.y);       \
        __half g2 = __float2half_rn(av1.z), g3 = __float2half_rn(av1.w);       \
        Ahi[(kpA + 8) * T2W + lrA] = pack_h2(g0, g1);                          \
        Ahi[(kpA + 9) * T2W + lrA] = pack_h2(g2, g3);                          \
        Alo[(kpA + 8) * T2W + lrA] = pack_f2h(av1.x - __half2float(g0), av1.y - __half2float(g1)); \
        Alo[(kpA + 9) * T2W + lrA] = pack_f2h(av1.z - __half2float(g2), av1.w - __half2float(g3)); \
        __half w00 = __float2half_rn(br0.x), w10 = __float2half_rn(br1.x);     \
        __half w01 = __float2half_rn(br0.y), w11 = __float2half_rn(br1.y);     \
        Bhi[kpB * T2W + nB]     = pack_h2(w00, w10);                           \
        Bhi[kpB * T2W + nB + 1] = pack_h2(w01, w11);                           \
        Blo[kpB * T2W + nB]     = pack_f2h(br0.x - __half2float(w00), br1.x - __half2float(w10)); \
        Blo[kpB * T2W + nB + 1] = pack_f2h(br0.y - __half2float(w01), br1.y - __half2float(w11)); \
        __half u00 = __float2half_rn(br2.x), u10 = __float2half_rn(br3.x);     \
        __half u01 = __float2half_rn(br2.y), u11 = __float2half_rn(br3.y);     \
        Bhi[(kpB + 8) * T2W + nB]     = pack_h2(u00, u10);                     \
        Bhi[(kpB + 8) * T2W + nB + 1] = pack_h2(u01, u11);                     \
        Blo[(kpB + 8) * T2W + nB]     = pack_f2h(br2.x - __half2float(u00), br3.x - __half2float(u10)); \
        Blo[(kpB + 8) * T2W + nB + 1] = pack_f2h(br2.y - __half2float(u01), br3.y - __half2float(u11)); \
    }

    H3_STORE(tiles);
    __syncthreads();

    for (int t = 0; t < nk; t++) {
        if (t + 1 < nk) {
            const float* a2 = Ap + (size_t)(t + 1) * 32;
            av0 = *(const float4*)(a2);
            av1 = *(const float4*)(a2 + 16);
            const float* w2 = Wp + (size_t)(t + 1) * 32 * N;
            br0 = *(const float2*)(w2);
            br1 = *(const float2*)(w2 + N);
            br2 = *(const float2*)(w2 + (size_t)16 * N);
            br3 = *(const float2*)(w2 + (size_t)17 * N);
        }
        int s = t & 1;
        const uint32_t* Ahi = tiles + s * H3BUF;
        const uint32_t* Alo = Ahi + T2SZ;
        const uint32_t* Bhi = Ahi + 2 * T2SZ;
        const uint32_t* Blo = Ahi + 3 * T2SZ;

#pragma unroll
        for (int sub = 0; sub < 2; sub++) {
            int ko = sub * 8;
            uint32_t ah[2][4], al[2][4], bh[4][2], bl[4][2];
#pragma unroll
            for (int mt = 0; mt < 2; mt++) {
                int m0 = wm + mt * 16 + gid;
                ah[mt][0] = Ahi[(ko + tig) * T2W + m0];
                ah[mt][1] = Ahi[(ko + tig) * T2W + m0 + 8];
                ah[mt][2] = Ahi[(ko + tig + 4) * T2W + m0];
                ah[mt][3] = Ahi[(ko + tig + 4) * T2W + m0 + 8];
                al[mt][0] = Alo[(ko + tig) * T2W + m0];
                al[mt][1] = Alo[(ko + tig) * T2W + m0 + 8];
                al[mt][2] = Alo[(ko + tig + 4) * T2W + m0];
                al[mt][3] = Alo[(ko + tig + 4) * T2W + m0 + 8];
            }
#pragma unroll
            for (int nt = 0; nt < 4; nt++) {
                int n0 = wn + nt * 8 + gid;
                bh[nt][0] = Bhi[(ko + tig) * T2W + n0];
                bh[nt][1] = Bhi[(ko + tig + 4) * T2W + n0];
                bl[nt][0] = Blo[(ko + tig) * T2W + n0];
                bl[nt][1] = Blo[(ko + tig + 4) * T2W + n0];
            }
#pragma unroll
            for (int mt = 0; mt < 2; mt++)
#pragma unroll
                for (int nt = 0; nt < 4; nt++)
                    mma_f16(acc[mt][nt], ah[mt], bh[nt]);
#pragma unroll
            for (int mt = 0; mt < 2; mt++)
#pragma unroll
                for (int nt = 0; nt < 4; nt++)
                    mma_f16(acc[mt][nt], ah[mt], bl[nt]);
#pragma unroll
            for (int mt = 0; mt < 2; mt++)
#pragma unroll
                for (int nt = 0; nt < 4; nt++)
                    mma_f16(acc[mt][nt], al[mt], bh[nt]);
        }

        if (t + 1 < nk) {
            uint32_t* nb = tiles + (s ^ 1) * H3BUF;
            H3_STORE(nb);
        }
        __syncthreads();
    }
#undef H3_STORE

#pragma unroll
    for (int mt = 0; mt < 2; mt++) {
#pragma unroll
        for (int c = 0; c < 4; c++) {
            int r = rowBase + wm + mt * 16 + gid + ((c & 2) ? 8 : 0);
#pragma unroll
            for (int nt = 0; nt < 4; nt++) {
                int cg = colBase + wn + nt * 8 + tig * 2 + (c & 1);
                float v = acc[mt][nt][c] + bias[cg];
                if (MODE == 1) v += Cp[(size_t)r * N + cg];
                Cp[(size_t)r * N + cg] = v;
            }
        }
    }
}

// ---------------- fp16 1-pass big-tile GEMM (128x256, BK=32, 512 thr) --------
#define HB_AW 136
#define HB_BW 264
#define HB_AT (16*HB_AW)
#define HB_BT (16*HB_BW)
#define HB_BUF (HB_AT+HB_BT)
#define SMEM_HB ((256 + 2*HB_BUF) * 4)   // 52224 B

template<int MODE>
__global__ void __launch_bounds__(512, 1)
gemm_hb(const void* __restrict__ A,
        const float* __restrict__ W0, const float* __restrict__ W1,
        const float* __restrict__ W2,
        const float* __restrict__ b0, const float* __restrict__ b1,
        const float* __restrict__ b2,
        void* __restrict__ C0, void* __restrict__ C1, void* __restrict__ C2,
        int Kd, int N, int layer) {
    constexpr bool A_HALF   = (MODE == 1 || MODE == 3);
    constexpr bool OUT_HALF = (MODE == 0 || MODE == 2);
    extern __shared__ float smf[];
    int*   s_tok = (int*)smf;
    float* s_wt  = smf + 128;
    uint32_t* tiles = (uint32_t*)(smf + 256);

    int tid = threadIdx.x;
    int rowBase = blockIdx.y * 128, colBase = blockIdx.x * 256;

    int e = 0, cnt = 0;
    const float* W;
    const float* bias;
    int z = 0;
    if (MODE >= 2) {
        e = blockIdx.z;
        cnt = g_counts[e];
        if (rowBase >= cnt) return;
        W    = W0 + (size_t)(layer * Ee + e) * Kd * N;
        bias = b0 + (size_t)(layer * Ee + e) * N;
        if (tid < 128) {
            int r = rowBase + tid;
            int rc = r < cnt ? r : cnt - 1;
            s_tok[tid] = g_tok[e * TOK + rc];
            s_wt[tid]  = g_wt [e * TOK + rc];
        }
        __syncthreads();
    } else {
        z = (MODE == 0) ? blockIdx.z : 0;
        W    = (z == 0) ? W0 : (z == 1 ? W1 : W2);
        bias = (z == 0) ? b0 : (z == 1 ? b1 : b2);
    }

    int lrA = tid >> 2, kcA4 = (tid & 3) << 2, kpA = (tid & 3) << 1;
    const float*  Apf = nullptr;
    const __half* Aph = nullptr;
    if (MODE == 2)      Apf = g_H + (size_t)s_tok[lrA] * Kd + kcA4;
    else if (MODE == 3) Aph = g_hidden_h + ((size_t)e * TOK + rowBase + lrA) * Kd + kcA4;
    else if (MODE == 1) Aph = (const __half*)A + (size_t)(rowBase + lrA) * Kd + kcA4;
    else                Apf = (const float*)A + (size_t)(rowBase + lrA) * Kd + kcA4;

    int kpB = tid >> 6, nB4 = (tid & 63) << 2;
    const float* Wp = W + (size_t)(2 * kpB) * N + colBase + nB4;

    int lane = tid & 31, warp = tid >> 5;
    int wm = (warp & 1) * 64, wn = (warp >> 1) * 32;
    int gid = lane >> 2, tig = lane & 3;

    float acc[4][4][4];
#pragma unroll
    for (int a = 0; a < 4; a++)
#pragma unroll
        for (int b3 = 0; b3 < 4; b3++)
#pragma unroll
            for (int c = 0; c < 4; c++) acc[a][b3][c] = 0.f;

    int nk = Kd / 32;
    float4 av0, av1, bv0, bv1, bv2, bv3;
    uint2 au0, au1;
    if (A_HALF) {
        au0 = *(const uint2*)(Aph);
        au1 = *(const uint2*)(Aph + 16);
    } else {
        av0 = *(const float4*)(Apf);
        av1 = *(const float4*)(Apf + 16);
    }
    bv0 = *(const float4*)(Wp);
    bv1 = *(const float4*)(Wp + N);
    bv2 = *(const float4*)(Wp + (size_t)16 * N);
    bv3 = *(const float4*)(Wp + (size_t)17 * N);

#define HB_STORE(BUF)                                                          \
    {                                                                          \
        uint32_t* As = (BUF);                                                  \
        uint32_t* Bs = (BUF) + HB_AT;                                          \
        if (A_HALF) {                                                          \
            As[kpA * HB_AW + lrA]       = au0.x;                               \
            As[(kpA + 1) * HB_AW + lrA] = au0.y;                               \
            As[(kpA + 8) * HB_AW + lrA] = au1.x;                               \
            As[(kpA + 9) * HB_AW + lrA] = au1.y;                               \
        } else {                                                               \
            As[kpA * HB_AW + lrA]       = pack_f2h(av0.x, av0.y);              \
            As[(kpA + 1) * HB_AW + lrA] = pack_f2h(av0.z, av0.w);              \
            As[(kpA + 8) * HB_AW + lrA] = pack_f2h(av1.x, av1.y);              \
            As[(kpA + 9) * HB_AW + lrA] = pack_f2h(av1.z, av1.w);              \
        }                                                                      \
        Bs[kpB * HB_BW + nB4 + 0] = pack_f2h(bv0.x, bv1.x);                    \
        Bs[kpB * HB_BW + nB4 + 1] = pack_f2h(bv0.y, bv1.y);                    \
        Bs[kpB * HB_BW + nB4 + 2] = pack_f2h(bv0.z, bv1.z);                    \
        Bs[kpB * HB_BW + nB4 + 3] = pack_f2h(bv0.w, bv1.w);                    \
        Bs[(kpB + 8) * HB_BW + nB4 + 0] = pack_f2h(bv2.x, bv3.x);              \
        Bs[(kpB + 8) * HB_BW + nB4 + 1] = pack_f2h(bv2.y, bv3.y);              \
        Bs[(kpB + 8) * HB_BW + nB4 + 2] = pack_f2h(bv2.z, bv3.z);              \
        Bs[(kpB + 8) * HB_BW + nB4 + 3] = pack_f2h(bv2.w, bv3.w);              \
    }

    HB_STORE(tiles);
    __syncthreads();

    for (int t = 0; t < nk; t++) {
        if (t + 1 < nk) {
            if (A_HALF) {
                au0 = *(const uint2*)(Aph + (size_t)(t + 1) * 32);
                au1 = *(const uint2*)(Aph + (size_t)(t + 1) * 32 + 16);
            } else {
                const float* a2 = Apf + (size_t)(t + 1) * 32;
                av0 = *(const float4*)(a2);
                av1 = *(const float4*)(a2 + 16);
            }
            const float* w2 = Wp + (size_t)(t + 1) * 32 * N;
            bv0 = *(const float4*)(w2);
            bv1 = *(const float4*)(w2 + N);
            bv2 = *(const float4*)(w2 + (size_t)16 * N);
            bv3 = *(const float4*)(w2 + (size_t)17 * N);
        }
        int s = t & 1;
        const uint32_t* As = tiles + s * HB_BUF;
        const uint32_t* Bs = As + HB_AT;

#pragma unroll
        for (int sub = 0; sub < 2; sub++) {
            int ko = sub * 8;
            uint32_t af[4][4], bf[4][2];
#pragma unroll
            for (int mt = 0; mt < 4; mt++) {
                int m0 = wm + mt * 16 + gid;
                af[mt][0] = As[(ko + tig) * HB_AW + m0];
                af[mt][1] = As[(ko + tig) * HB_AW + m0 + 8];
                af[mt][2] = As[(ko + tig + 4) * HB_AW + m0];
                af[mt][3] = As[(ko + tig + 4) * HB_AW + m0 + 8];
            }
#pragma unroll
            for (int nt = 0; nt < 4; nt++) {
                int n0 = wn + nt * 8 + gid;
                bf[nt][0] = Bs[(ko + tig) * HB_BW + n0];
                bf[nt][1] = Bs[(ko + tig + 4) * HB_BW + n0];
            }
#pragma unroll
            for (int mt = 0; mt < 4; mt++)
#pragma unroll
                for (int nt = 0; nt < 4; nt++)
                    mma_f16(acc[mt][nt], af[mt], bf[nt]);
        }

        if (t + 1 < nk) {
            uint32_t* nb = tiles + (s ^ 1) * HB_BUF;
            HB_STORE(nb);
        }
        __syncthreads();
    }
#undef HB_STORE

    if (OUT_HALF) {
        __half* outh = nullptr;
        if (MODE == 0) outh = (__half*)((z == 0) ? C0 : (z == 1 ? C1 : C2));
#pragma unroll
        for (int mt = 0; mt < 4; mt++) {
#pragma unroll
            for (int rp = 0; rp < 2; rp++) {
                int r = rowBase + wm + mt * 16 + gid + rp * 8;
                if (MODE == 2 && r >= cnt) continue;
#pragma unroll
                for (int nt = 0; nt < 4; nt++) {
                    int cg0 = colBase + wn + nt * 8 + tig * 2;
                    float v0 = acc[mt][nt][rp * 2]     + bias[cg0];
                    float v1 = acc[mt][nt][rp * 2 + 1] + bias[cg0 + 1];
                    if (MODE == 2) { v0 = gelu_exact(v0); v1 = gelu_exact(v1); }
                    uint32_t pk = pack_f2h(v0, v1);
                    if (MODE == 0)
                        *(uint32_t*)&outh[(size_t)r * N + cg0] = pk;
                    else
                        *(uint32_t*)&g_hidden_h[((size_t)e * TOK + r) * N + cg0] = pk;
                }
            }
        }
    } else {
        float* Cpf = (float*)C0;
#pragma unroll
        for (int mt = 0; mt < 4; mt++) {
#pragma unroll
            for (int c = 0; c < 4; c++) {
                int rl = wm + mt * 16 + gid + ((c & 2) ? 8 : 0);
                int r  = rowBase + rl;
#pragma unroll
                for (int nt = 0; nt < 4; nt++) {
                    int cg = colBase + wn + nt * 8 + tig * 2 + (c & 1);
                    float v = acc[mt][nt][c] + bias[cg];
                    if (MODE == 1) {
                        Cpf[(size_t)r * N + cg] = v + Cpf[(size_t)r * N + cg];
                    } else {
                        g_moeout[((size_t)(e * TOK + r)) * N + cg] = v * s_wt[rl];
                    }
                }
            }
        }
    }
}

// ---------------- fp16 split flash attention (layer 0, qb-paired) ------------
#define FQ2 (32*136)
#define FK2 (32*72)
#define FV2 (32*72)
#define FP2 (32*136)
#define FL2_TOT (FQ2+FK2+FV2+FP2)
#define FL2_SMEM1 (FL2_TOT*8)

template<int SPLIT>
__global__ void __launch_bounds__(256, 2)
flash_h() {
    extern __shared__ uint32_t fu[];
    uint32_t* Qh = fu;
    uint32_t* Ql = Qh + FQ2;
    uint32_t* Kh = Qh + FQ2 * (SPLIT + 1);
    uint32_t* Kl = Kh + FK2;
    uint32_t* Vh = Kh + FK2 * (SPLIT + 1);
    uint32_t* Vl = Vh + FV2;
    uint32_t* Ph = Vh + FV2 * (SPLIT + 1);
    uint32_t* Pl = Ph + FP2;

    int h = blockIdx.y, b = blockIdx.z;
    int tid = threadIdx.x, warp = tid >> 5, lane = tid & 31;
    int gid = lane >> 2, tig = lane & 3;
    int mrow = warp * 16 + gid;

    for (int hf = 0; hf < 2; hf++) {
        int qb = (hf == 0) ? (7 - (int)blockIdx.x) : (int)blockIdx.x;

        for (int i = tid; i < 2048; i += 256) {
            int r = i >> 4, d4 = (i & 15) << 2, dp = (i & 15) << 1;
            float4 v = *(const float4*)&g_Q[((size_t)(b * Sq + qb * 128 + r)) * Dq + h * HD + d4];
            __half h0 = __float2half_rn(v.x), h1 = __float2half_rn(v.y);
            __half h2 = __float2half_rn(v.z), h3 = __float2half_rn(v.w);
            Qh[dp * 136 + r]       = pack_h2(h0, h1);
            Qh[(dp + 1) * 136 + r] = pack_h2(h2, h3);
            if (SPLIT) {
                Ql[dp * 136 + r]       = pack_f2h(v.x - __half2float(h0), v.y - __half2float(h1));
                Ql[(dp + 1) * 136 + r] = pack_f2h(v.z - __half2float(h2), v.w - __half2float(h3));
            }
        }

        float mA = -1e30f, mB = -1e30f, lA = 0.f, lB = 0.f;
        float o[8][4];
#pragma unroll
        for (int nt = 0; nt < 8; nt++)
#pragma unroll
            for (int c = 0; c < 4; c++) o[nt][c] = 0.f;

        int nkt = 2 * qb + 2;
        for (int kt = 0; kt < nkt; kt++) {
            __syncthreads();
            for (int i = tid; i < 1024; i += 256) {
                int r = i >> 4, d4 = (i & 15) << 2, dp = (i & 15) << 1;
                size_t base = ((size_t)(b * Sq + kt * 64 + r)) * Dq + h * HD + d4;
                float4 kv = *(const float4*)&g_K[base];
                __half h0 = __float2half_rn(kv.x), h1 = __float2half_rn(kv.y);
                __half h2 = __float2half_rn(kv.z), h3 = __float2half_rn(kv.w);
                Kh[dp * 72 + r]       = pack_h2(h0, h1);
                Kh[(dp + 1) * 72 + r] = pack_h2(h2, h3);
                if (SPLIT) {
                    Kl[dp * 72 + r]       = pack_f2h(kv.x - __half2float(h0), kv.y - __half2float(h1));
                    Kl[(dp + 1) * 72 + r] = pack_f2h(kv.z - __half2float(h2), kv.w - __half2float(h3));
                }
            }
            float4 vr0[2], vr1[2];
#pragma unroll
            for (int ii = 0; ii < 2; ii++) {
                int i = tid + ii * 256;
                int kp = i >> 4, d4 = (i & 15) << 2;
                size_t base0 = ((size_t)(b * Sq + kt * 64 + 2 * kp)) * Dq + h * HD + d4;
                vr0[ii] = *(const float4*)&g_V[base0];
                vr1[ii] = *(const float4*)&g_V[base0 + Dq];
            }
            __syncthreads();

            float s[8][4];
#pragma unroll
            for (int nt = 0; nt < 8; nt++)
#pragma unroll
                for (int c = 0; c < 4; c++) s[nt][c] = 0.f;

#pragma unroll
            for (int ks = 0; ks < 4; ks++) {
                int kp0 = 8 * ks + tig, kp1 = 8 * ks + tig + 4;
                uint32_t a[4], al[4];
                a[0] = Qh[kp0 * 136 + mrow];
                a[1] = Qh[kp0 * 136 + mrow + 8];
                a[2] = Qh[kp1 * 136 + mrow];
                a[3] = Qh[kp1 * 136 + mrow + 8];
                if (SPLIT) {
                    al[0] = Ql[kp0 * 136 + mrow];
                    al[1] = Ql[kp0 * 136 + mrow + 8];
                    al[2] = Ql[kp1 * 136 + mrow];
                    al[3] = Ql[kp1 * 136 + mrow + 8];
                }
#pragma unroll
                for (int gq = 0; gq < 2; gq++) {
                    uint32_t bb[4][2], bl[4][2];
#pragma unroll
                    for (int j = 0; j < 4; j++) {
                        int n0 = (gq * 4 + j) * 8 + gid;
                        bb[j][0] = Kh[kp0 * 72 + n0];
                        bb[j][1] = Kh[kp1 * 72 + n0];
                        if (SPLIT) {
                            bl[j][0] = Kl[kp0 * 72 + n0];
                            bl[j][1] = Kl[kp1 * 72 + n0];
                        }
                    }
#pragma unroll
                    for (int j = 0; j < 4; j++) mma_f16(s[gq * 4 + j], a, bb[j]);
                    if (SPLIT) {
#pragma unroll
                        for (int j = 0; j < 4; j++) mma_f16(s[gq * 4 + j], a, bl[j]);
#pragma unroll
                        for (int j = 0; j < 4; j++) mma_f16(s[gq * 4 + j], al, bb[j]);
                    }
                }
            }

            int rowg = qb * 128 + warp * 16 + gid;
            if (kt * 64 + 63 > rowg) {
#pragma unroll
                for (int nt = 0; nt < 8; nt++)
#pragma unroll
                    for (int c = 0; c < 4; c++) {
                        int col = kt * 64 + nt * 8 + 2 * tig + (c & 1);
                        int row = rowg + ((c & 2) ? 8 : 0);
                        float sv = s[nt][c] * 0.125f;
                        s[nt][c] = (col > row) ? -1e30f : sv;
                    }
            } else {
#pragma unroll
                for (int nt = 0; nt < 8; nt++)
#pragma unroll
                    for (int c = 0; c < 4; c++) s[nt][c] *= 0.125f;
            }

            float rmA = -1e30f, rmB = -1e30f;
#pragma unroll
            for (int nt = 0; nt < 8; nt++) {
                rmA = fmaxf(rmA, fmaxf(s[nt][0], s[nt][1]));
                rmB = fmaxf(rmB, fmaxf(s[nt][2], s[nt][3]));
            }
#pragma unroll
            for (int off = 1; off < 4; off <<= 1) {
                rmA = fmaxf(rmA, __shfl_xor_sync(0xffffffffu, rmA, off));
                rmB = fmaxf(rmB, __shfl_xor_sync(0xffffffffu, rmB, off));
            }
            float mnA = fmaxf(mA, rmA), mnB = fmaxf(mB, rmB);
            float alA = __expf(mA - mnA), alB = __expf(mB - mnB);
            float rsA = 0.f, rsB = 0.f;
#pragma unroll
            for (int nt = 0; nt < 8; nt++) {
                s[nt][0] = __expf(s[nt][0] - mnA); rsA += s[nt][0];
                s[nt][1] = __expf(s[nt][1] - mnA); rsA += s[nt][1];
                s[nt][2] = __expf(s[nt][2] - mnB); rsB += s[nt][2];
                s[nt][3] = __expf(s[nt][3] - mnB); rsB += s[nt][3];
            }
#pragma unroll
            for (int off = 1; off < 4; off <<= 1) {
                rsA += __shfl_xor_sync(0xffffffffu, rsA, off);
                rsB += __shfl_xor_sync(0xffffffffu, rsB, off);
            }
            lA = lA * alA + rsA; mA = mnA;
            lB = lB * alB + rsB; mB = mnB;
#pragma unroll
            for (int nt = 0; nt < 8; nt++) {
                o[nt][0] *= alA; o[nt][1] *= alA;
                o[nt][2] *= alB; o[nt][3] *= alB;
            }

#pragma unroll
            for (int nt = 0; nt < 8; nt++) {
                int kpP = nt * 4 + tig;
                __half p0 = __float2half_rn(s[nt][0]), p1 = __float2half_rn(s[nt][1]);
                __half p2 = __float2half_rn(s[nt][2]), p3 = __float2half_rn(s[nt][3]);
                Ph[kpP * 136 + mrow]     = pack_h2(p0, p1);
                Ph[kpP * 136 + mrow + 8] = pack_h2(p2, p3);
                if (SPLIT) {
                    Pl[kpP * 136 + mrow]     = pack_f2h(s[nt][0] - __half2float(p0),
                                                        s[nt][1] - __half2float(p1));
                    Pl[kpP * 136 + mrow + 8] = pack_f2h(s[nt][2] - __half2float(p2),
                                                        s[nt][3] - __half2float(p3));
                }
            }
#pragma unroll
            for (int ii = 0; ii < 2; ii++) {
                int i = tid + ii * 256;
                int kp = i >> 4, d4 = (i & 15) << 2;
                float a0[4] = {vr0[ii].x, vr0[ii].y, vr0[ii].z, vr0[ii].w};
                float a1[4] = {vr1[ii].x, vr1[ii].y, vr1[ii].z, vr1[ii].w};
#pragma unroll
                for (int j = 0; j < 4; j++) {
                    __half p0 = __float2half_rn(a0[j]), p1 = __float2half_rn(a1[j]);
                    Vh[kp * 72 + d4 + j] = pack_h2(p0, p1);
                    if (SPLIT)
                        Vl[kp * 72 + d4 + j] = pack_f2h(a0[j] - __half2float(p0),
                                                        a1[j] - __half2float(p1));
                }
            }
            __syncthreads();

#pragma unroll
            for (int ks = 0; ks < 4; ks++) {
                int kp0 = 8 * ks + tig, kp1 = 8 * ks + tig + 4;
                uint32_t a[4], al[4];
                a[0] = Ph[kp0 * 136 + mrow];
                a[1] = Ph[kp0 * 136 + mrow + 8];
                a[2] = Ph[kp1 * 136 + mrow];
                a[3] = Ph[kp1 * 136 + mrow + 8];
                if (SPLIT) {
                    al[0] = Pl[kp0 * 136 + mrow];
                    al[1] = Pl[kp0 * 136 + mrow + 8];
                    al[2] = Pl[kp1 * 136 + mrow];
                    al[3] = Pl[kp1 * 136 + mrow + 8];
                }
#pragma unroll
                for (int gq = 0; gq < 2; gq++) {
                    uint32_t bb[4][2], bl[4][2];
#pragma unroll
                    for (int j = 0; j < 4; j++) {
                        int n0 = (gq * 4 + j) * 8 + gid;
                        bb[j][0] = Vh[kp0 * 72 + n0];
                        bb[j][1] = Vh[kp1 * 72 + n0];
                        if (SPLIT) {
                            bl[j][0] = Vl[kp0 * 72 + n0];
                            bl[j][1] = Vl[kp1 * 72 + n0];
                        }
                    }
#pragma unroll
                    for (int j = 0; j < 4; j++) mma_f16(o[gq * 4 + j], a, bb[j]);
                    if (SPLIT) {
#pragma unroll
                        for (int j = 0; j < 4; j++) mma_f16(o[gq * 4 + j], a, bl[j]);
#pragma unroll
                        for (int j = 0; j < 4; j++) mma_f16(o[gq * 4 + j], al, bb[j]);
                    }
                }
            }
        }

        float invA = 1.0f / lA, invB = 1.0f / lB;
        size_t rbase0 = ((size_t)(b * Sq + qb * 128 + warp * 16 + gid)) * Dq + h * HD;
        size_t rbase1 = rbase0 + (size_t)8 * Dq;
#pragma unroll
        for (int nt = 0; nt < 8; nt++) {
            int d0 = nt * 8 + 2 * tig;
            *(float2*)&g_Y[rbase0 + d0] = make_float2(o[nt][0] * invA, o[nt][1] * invA);
            *(float2*)&g_Y[rbase1 + d0] = make_float2(o[nt][2] * invB, o[nt][3] * invB);
        }
        __syncthreads();
    }
}

// ---------------- fp16 1-pass flash (layer 1, pipelined, qb-paired) ----------
#define F0_Q  (32*136)
#define F0_K  (32*72)
#define F0_V  (32*72)
#define F0_P  (32*136)
#define FL0_SMEM ((F0_Q + F0_K + 2*F0_V + F0_P) * 4)   // 62464 B

__global__ void __launch_bounds__(256, 2)
flash_h0() {
    extern __shared__ uint32_t fu[];
    uint32_t* Qh = fu;
    uint32_t* Kh = Qh + F0_Q;
    uint32_t* Vh0 = Kh + F0_K;
    uint32_t* Vh1 = Vh0 + F0_V;
    uint32_t* Ph = Vh1 + F0_V;

    int h = blockIdx.y, b = blockIdx.z;
    int tid = threadIdx.x, warp = tid >> 5, lane = tid & 31;
    int gid = lane >> 2, tig = lane & 3;
    int mrow = warp * 16 + gid;

    for (int hf = 0; hf < 2; hf++) {
        int qb = (hf == 0) ? (7 - (int)blockIdx.x) : (int)blockIdx.x;
        if (hf) __syncthreads();

        for (int i = tid; i < 1024; i += 256) {
            int r = i >> 3, d8 = (i & 7) << 3, dp = d8 >> 1;
            uint4 u = *(const uint4*)&g_Qh[((size_t)(b * Sq + qb * 128 + r)) * Dq + h * HD + d8];
            Qh[(dp + 0) * 136 + r] = u.x;
            Qh[(dp + 1) * 136 + r] = u.y;
            Qh[(dp + 2) * 136 + r] = u.z;
            Qh[(dp + 3) * 136 + r] = u.w;
        }
        for (int i = tid; i < 512; i += 256) {
            int r = i >> 3, d8 = (i & 7) << 3, dp = d8 >> 1;
            uint4 u = *(const uint4*)&g_Kh[((size_t)(b * Sq + r)) * Dq + h * HD + d8];
            Kh[(dp + 0) * 72 + r] = u.x;
            Kh[(dp + 1) * 72 + r] = u.y;
            Kh[(dp + 2) * 72 + r] = u.z;
            Kh[(dp + 3) * 72 + r] = u.w;
        }
        for (int i = tid; i < 512; i += 256) {
            int kp = i >> 4, d4 = (i & 15) << 2;
            size_t base0 = ((size_t)(b * Sq + 2 * kp)) * Dq + h * HD + d4;
            uint2 a = *(const uint2*)&g_Vh[base0];
            uint2 c = *(const uint2*)&g_Vh[base0 + Dq];
            Vh0[kp * 72 + d4 + 0] = __byte_perm(a.x, c.x, 0x5410);
            Vh0[kp * 72 + d4 + 1] = __byte_perm(a.x, c.x, 0x7632);
            Vh0[kp * 72 + d4 + 2] = __byte_perm(a.y, c.y, 0x5410);
            Vh0[kp * 72 + d4 + 3] = __byte_perm(a.y, c.y, 0x7632);
        }
        __syncthreads();

        float mA = -1e30f, mB = -1e30f, lA = 0.f, lB = 0.f;
        float o[8][4];
#pragma unroll
        for (int nt = 0; nt < 8; nt++)
#pragma unroll
            for (int c = 0; c < 4; c++) o[nt][c] = 0.f;

        int nkt = 2 * qb + 2;
        for (int kt = 0; kt < nkt; kt++) {
            uint32_t* Vcur = (kt & 1) ? Vh1 : Vh0;
            uint32_t* Vnxt = (kt & 1) ? Vh0 : Vh1;

            uint4 kreg[2];
            uint2 va[2], vb[2];
            bool more = (kt + 1 < nkt);
            if (more) {
#pragma unroll
                for (int ii = 0; ii < 2; ii++) {
                    int i = tid + ii * 256;
                    int r = i >> 3, d8 = (i & 7) << 3;
                    kreg[ii] = *(const uint4*)&g_Kh[((size_t)(b * Sq + (kt + 1) * 64 + r)) * Dq + h * HD + d8];
                }
#pragma unroll
                for (int ii = 0; ii < 2; ii++) {
                    int i = tid + ii * 256;
                    int kp = i >> 4, d4 = (i & 15) << 2;
                    size_t base0 = ((size_t)(b * Sq + (kt + 1) * 64 + 2 * kp)) * Dq + h * HD + d4;
                    va[ii] = *(const uint2*)&g_Vh[base0];
                    vb[ii] = *(const uint2*)&g_Vh[base0 + Dq];
                }
            }

            float s[8][4];
#pragma unroll
            for (int nt = 0; nt < 8; nt++)
#pragma unroll
                for (int c = 0; c < 4; c++) s[nt][c] = 0.f;
#pragma unroll
            for (int ks = 0; ks < 4; ks++) {
                int kp0 = 8 * ks + tig, kp1 = 8 * ks + tig + 4;
                uint32_t a[4];
                a[0] = Qh[kp0 * 136 + mrow];
                a[1] = Qh[kp0 * 136 + mrow + 8];
                a[2] = Qh[kp1 * 136 + mrow];
                a[3] = Qh[kp1 * 136 + mrow + 8];
#pragma unroll
                for (int gq = 0; gq < 2; gq++) {
                    uint32_t bb[4][2];
#pragma unroll
                    for (int j = 0; j < 4; j++) {
                        int n0 = (gq * 4 + j) * 8 + gid;
                        bb[j][0] = Kh[kp0 * 72 + n0];
                        bb[j][1] = Kh[kp1 * 72 + n0];
                    }
#pragma unroll
                    for (int j = 0; j < 4; j++) mma_f16(s[gq * 4 + j], a, bb[j]);
                }
            }

            int rowg = qb * 128 + warp * 16 + gid;
            if (kt * 64 + 63 > rowg) {
#pragma unroll
                for (int nt = 0; nt < 8; nt++)
#pragma unroll
                    for (int c = 0; c < 4; c++) {
                        int col = kt * 64 + nt * 8 + 2 * tig + (c & 1);
                        int row = rowg + ((c & 2) ? 8 : 0);
                        float sv = s[nt][c] * 0.125f;
                        s[nt][c] = (col > row) ? -1e30f : sv;
                    }
            } else {
#pragma unroll
                for (int nt = 0; nt < 8; nt++)
#pragma unroll
                    for (int c = 0; c < 4; c++) s[nt][c] *= 0.125f;
            }

            float rmA = -1e30f, rmB = -1e30f;
#pragma unroll
            for (int nt = 0; nt < 8; nt++) {
                rmA = fmaxf(rmA, fmaxf(s[nt][0], s[nt][1]));
                rmB = fmaxf(rmB, fmaxf(s[nt][2], s[nt][3]));
            }
#pragma unroll
            for (int off = 1; off < 4; off <<= 1) {
                rmA = fmaxf(rmA, __shfl_xor_sync(0xffffffffu, rmA, off));
                rmB = fmaxf(rmB, __shfl_xor_sync(0xffffffffu, rmB, off));
            }
            float mnA = fmaxf(mA, rmA), mnB = fmaxf(mB, rmB);
            float alA = __expf(mA - mnA), alB = __expf(mB - mnB);
            float rsA = 0.f, rsB = 0.f;
#pragma unroll
            for (int nt = 0; nt < 8; nt++) {
                s[nt][0] = __expf(s[nt][0] - mnA); rsA += s[nt][0];
                s[nt][1] = __expf(s[nt][1] - mnA); rsA += s[nt][1];
                s[nt][2] = __expf(s[nt][2] - mnB); rsB += s[nt][2];
                s[nt][3] = __expf(s[nt][3] - mnB); rsB += s[nt][3];
            }
#pragma unroll
            for (int off = 1; off < 4; off <<= 1) {
                rsA += __shfl_xor_sync(0xffffffffu, rsA, off);
                rsB += __shfl_xor_sync(0xffffffffu, rsB, off);
            }
            lA = lA * alA + rsA; mA = mnA;
            lB = lB * alB + rsB; mB = mnB;
#pragma unroll
            for (int nt = 0; nt < 8; nt++) {
                o[nt][0] *= alA; o[nt][1] *= alA;
                o[nt][2] *= alB; o[nt][3] *= alB;
            }

            __syncthreads();

#pragma unroll
            for (int nt = 0; nt < 8; nt++) {
                int kpP = nt * 4 + tig;
                Ph[kpP * 136 + mrow]     = pack_f2h(s[nt][0], s[nt][1]);
                Ph[kpP * 136 + mrow + 8] = pack_f2h(s[nt][2], s[nt][3]);
            }
            if (more) {
#pragma unroll
                for (int ii = 0; ii < 2; ii++) {
                    int i = tid + ii * 256;
                    int r = i >> 3, dp = ((i & 7) << 3) >> 1;
                    Kh[(dp + 0) * 72 + r] = kreg[ii].x;
                    Kh[(dp + 1) * 72 + r] = kreg[ii].y;
                    Kh[(dp + 2) * 72 + r] = kreg[ii].z;
                    Kh[(dp + 3) * 72 + r] = kreg[ii].w;
                }
#pragma unroll
                for (int ii = 0; ii < 2; ii++) {
                    int i = tid + ii * 256;
                    int kp = i >> 4, d4 = (i & 15) << 2;
                    Vnxt[kp * 72 + d4 + 0] = __byte_perm(va[ii].x, vb[ii].x, 0x5410);
                    Vnxt[kp * 72 + d4 + 1] = __byte_perm(va[ii].x, vb[ii].x, 0x7632);
                    Vnxt[kp * 72 + d4 + 2] = __byte_perm(va[ii].y, vb[ii].y, 0x5410);
                    Vnxt[kp * 72 + d4 + 3] = __byte_perm(va[ii].y, vb[ii].y, 0x7632);
                }
            }
            __syncthreads();

#pragma unroll
            for (int ks = 0; ks < 4; ks++) {
                int kp0 = 8 * ks + tig, kp1 = 8 * ks + tig + 4;
                uint32_t a[4];
                a[0] = Ph[kp0 * 136 + mrow];
                a[1] = Ph[kp0 * 136 + mrow + 8];
                a[2] = Ph[kp1 * 136 + mrow];
                a[3] = Ph[kp1 * 136 + mrow + 8];
#pragma unroll
                for (int gq = 0; gq < 2; gq++) {
                    uint32_t bb[4][2];
#pragma unroll
                    for (int j = 0; j < 4; j++) {
                        int n0 = (gq * 4 + j) * 8 + gid;
                        bb[j][0] = Vcur[kp0 * 72 + n0];
                        bb[j][1] = Vcur[kp1 * 72 + n0];
                    }
#pragma unroll
                    for (int j = 0; j < 4; j++) mma_f16(o[gq * 4 + j], a, bb[j]);
                }
            }
        }

        float invA = 1.0f / lA, invB = 1.0f / lB;
        size_t rbase0 = ((size_t)(b * Sq + qb * 128 + warp * 16 + gid)) * Dq + h * HD;
        size_t rbase1 = rbase0 + (size_t)8 * Dq;
#pragma unroll
        for (int nt = 0; nt < 8; nt++) {
            int d0 = nt * 8 + 2 * tig;
            *(uint32_t*)&g_Yh[rbase0 + d0] = pack_f2h(o[nt][0] * invA, o[nt][1] * invA);
            *(uint32_t*)&g_Yh[rbase1 + d0] = pack_f2h(o[nt][2] * invB, o[nt][3] * invB);
        }
    }
}

// ---------------- gating -----------------------------------------------------
// token mode: top-2 + assignment fused (counts zeroed by preceding ln2 launch)
__global__ void gate_token_kernel(const float* __restrict__ gw,
                                  const float* __restrict__ gb, int layer) {
    int t = blockIdx.x * 4 + (threadIdx.x >> 5);
    int lane = threadIdx.x & 31;
    if (t >= TOK) return;
    const float* hrow = g_H + (size_t)t * Dq;
    const float* gwl = gw + (size_t)layer * Dq * Ee;
    float acc[Ee] = {};
    for (int d = lane; d < Dq; d += 32) {
        float hv = hrow[d];
        const float* g = gwl + (size_t)d * Ee;
#pragma unroll
        for (int e = 0; e < Ee; e++) acc[e] += hv * g[e];
    }
#pragma unroll
    for (int e = 0; e < Ee; e++)
        for (int off = 16; off; off >>= 1)
            acc[e] += __shfl_xor_sync(0xffffffffu, acc[e], off);
    if (lane == 0) {
        float lg[Ee];
#pragma unroll
        for (int e = 0; e < Ee; e++) lg[e] = acc[e] + gb[layer * Ee + e];
        int i1, i2; float w1, w2;
        top2_of8(lg, i1, i2, w1, w2);
        int s1 = atomicAdd(&g_counts[i1], 1);
        g_tok[i1 * TOK + s1] = t; g_wt[i1 * TOK + s1] = w1;
        g_islot[t * 2] = i1 * TOK + s1;
        int s2 = atomicAdd(&g_counts[i2], 1);
        g_tok[i2 * TOK + s2] = t; g_wt[i2 * TOK + s2] = w2;
        g_islot[t * 2 + 1] = i2 * TOK + s2;
    }
}

__global__ void xmean_kernel() {
    int b = blockIdx.y;
    int d = blockIdx.x * 256 + threadIdx.x;
    float s = 0.f;
    for (int ss = 0; ss < Sq; ss++)
        s += g_H[((size_t)(b * Sq + ss)) * Dq + d];
    g_xmean[b * Dq + d] = s * (1.0f / Sq);
}

__global__ void gate_seq_kernel(const float* __restrict__ gw,
                                const float* __restrict__ gb, int layer) {
    int b = blockIdx.x;
    int tid = threadIdx.x, e = tid >> 5, lane = tid & 31;
    const float* gwl = gw + (size_t)layer * Dq * Ee;
    float acc = 0.f;
    for (int d = lane; d < Dq; d += 32)
        acc += g_xmean[b * Dq + d] * gwl[(size_t)d * Ee + e];
    for (int off = 16; off; off >>= 1)
        acc += __shfl_xor_sync(0xffffffffu, acc, off);
    __shared__ float lg[Ee];
    if (lane == 0) lg[e] = acc + gb[layer * Ee + e];
    __syncthreads();
    if (tid == 0) {
        int i1, i2; float w1, w2;
        top2_of8(lg, i1, i2, w1, w2);
        g_bsel[b * 2] = i1; g_bsel[b * 2 + 1] = i2;
        g_bw[b * 2] = w1;  g_bw[b * 2 + 1] = w2;
    }
}

__global__ void assign_seq_kernel() {
    int t = blockIdx.x * 256 + threadIdx.x;
    if (t >= TOK) return;
    int b = t / Sq;
    int e1 = g_bsel[b * 2], e2 = g_bsel[b * 2 + 1];
    float w1 = g_bw[b * 2], w2 = g_bw[b * 2 + 1];
    int s1 = atomicAdd(&g_counts[e1], 1);
    g_tok[e1 * TOK + s1] = t; g_wt[e1 * TOK + s1] = w1;
    g_islot[t * 2] = e1 * TOK + s1;
    int s2 = atomicAdd(&g_counts[e2], 1);
    g_tok[e2 * TOK + s2] = t; g_wt[e2 * TOK + s2] = w2;
    g_islot[t * 2 + 1] = e2 * TOK + s2;
}

// ---------------- host side --------------------------------------------------
extern "C" void kernel_launch(void* const* d_in, const int* in_sizes, int n_in,
                              void* d_out, int out_size) {
    const float* x      = (const float*)d_in[0];
    const float* ln1_w  = (const float*)d_in[1];
    const float* ln1_b  = (const float*)d_in[2];
    const float* ln2_w  = (const float*)d_in[3];
    const float* ln2_b  = (const float*)d_in[4];
    const float* wq     = (const float*)d_in[5];
    const float* wk     = (const float*)d_in[6];
    const float* wv     = (const float*)d_in[7];
    const float* wo     = (const float*)d_in[8];
    const float* bq     = (const float*)d_in[9];
    const float* bk     = (const float*)d_in[10];
    const float* bv     = (const float*)d_in[11];
    const float* bo     = (const float*)d_in[12];
    const float* gate_w = (const float*)d_in[13];
    const float* gate_b = (const float*)d_in[14];
    const float* e_w1   = (const float*)d_in[15];
    const float* e_b1   = (const float*)d_in[16];
    const float* e_w2   = (const float*)d_in[17];
    const float* e_b2   = (const float*)d_in[18];

    float *Xp, *Hp, *Qp, *Kp, *Vp, *Yp;
    void *Qhp, *Khp, *Vhp, *Yhp;
    cudaGetSymbolAddress((void**)&Xp, g_X);
    cudaGetSymbolAddress((void**)&Hp, g_H);
    cudaGetSymbolAddress((void**)&Qp, g_Q);
    cudaGetSymbolAddress((void**)&Kp, g_K);
    cudaGetSymbolAddress((void**)&Vp, g_V);
    cudaGetSymbolAddress((void**)&Yp, g_Y);
    cudaGetSymbolAddress(&Qhp, g_Qh);
    cudaGetSymbolAddress(&Khp, g_Kh);
    cudaGetSymbolAddress(&Vhp, g_Vh);
    cudaGetSymbolAddress(&Yhp, g_Yh);

    static int attr_set = 0;
    if (!attr_set) {
        cudaFuncSetAttribute(gemm_h3<0>, cudaFuncAttributeMaxDynamicSharedMemorySize, SMEM_H3);
        cudaFuncSetAttribute(gemm_h3<1>, cudaFuncAttributeMaxDynamicSharedMemorySize, SMEM_H3);
        cudaFuncSetAttribute(gemm_hb<0>, cudaFuncAttributeMaxDynamicSharedMemorySize, SMEM_HB);
        cudaFuncSetAttribute(gemm_hb<1>, cudaFuncAttributeMaxDynamicSharedMemorySize, SMEM_HB);
        cudaFuncSetAttribute(gemm_hb<2>, cudaFuncAttributeMaxDynamicSharedMemorySize, SMEM_HB);
        cudaFuncSetAttribute(gemm_hb<3>, cudaFuncAttributeMaxDynamicSharedMemorySize, SMEM_HB);
        cudaFuncSetAttribute(flash_h<1>, cudaFuncAttributeMaxDynamicSharedMemorySize, FL2_SMEM1);
        cudaFuncSetAttribute(flash_h0,   cudaFuncAttributeMaxDynamicSharedMemorySize, FL0_SMEM);
        attr_set = 1;
    }

    const size_t DD = (size_t)Dq * Dq;
    const int nelem = TOK * Dq;

    for (int l = 0; l < Ll; l++) {
        const float* WQ = wq + l * DD;
        const float* WK = wk + l * DD;
        const float* WV = wv + l * DD;
        const float* WO = wo + l * DD;
        const float* BQ = bq + (size_t)l * Dq;
        const float* BK = bk + (size_t)l * Dq;
        const float* BV = bv + (size_t)l * Dq;
        const float* BO = bo + (size_t)l * Dq;

        if (l == 0)
            ln_in_kernel<<<TOK, 256>>>(x, ln1_w + (size_t)l * Dq, ln1_b + (size_t)l * Dq);
        else
            ln_combine_kernel<<<TOK, 256>>>(ln1_w + (size_t)l * Dq, ln1_b + (size_t)l * Dq);

        if (l == 0) {
            gemm_h3<0><<<dim3(8, 32, 3), 512, SMEM_H3>>>(
                Hp, WQ, WK, WV, BQ, BK, BV, Qp, Kp, Vp, Dq, Dq);
            flash_h<1><<<dim3(4, Hh, Bq), 256, FL2_SMEM1>>>();
            gemm_h3<1><<<dim3(8, 32), 512, SMEM_H3>>>(
                Yp, WO, nullptr, nullptr, BO, nullptr, nullptr, Xp, nullptr, nullptr, Dq, Dq);
        } else {
            gemm_hb<0><<<dim3(4, 32, 3), 512, SMEM_HB>>>(
                Hp, WQ, WK, WV, BQ, BK, BV, Qhp, Khp, Vhp, Dq, Dq, l);
            flash_h0<<<dim3(4, Hh, Bq), 256, FL0_SMEM>>>();
            gemm_hb<1><<<dim3(4, 32), 512, SMEM_HB>>>(
                Yhp, WO, nullptr, nullptr, BO, nullptr, nullptr, Xp, nullptr, nullptr, Dq, Dq, l);
        }

        // ln2 zeroes MoE counts (consumed by the gate/assign launches that follow)
        ln_kernel_t<1><<<TOK, 256>>>(ln2_w + (size_t)l * Dq, ln2_b + (size_t)l * Dq);
        if (l % 2 == 0) {
            gate_token_kernel<<<TOK / 4, 128>>>(gate_w, gate_b, l);   // fused assign
        } else {
            xmean_kernel<<<dim3(Dq / 256, Bq), 256>>>();
            gate_seq_kernel<<<Bq, 256>>>(gate_w, gate_b, l);
            assign_seq_kernel<<<TOK / 256, 256>>>();
        }
        gemm_hb<2><<<dim3(DFFq / 256, TOK / 128, Ee), 512, SMEM_HB>>>(
            nullptr, e_w1, nullptr, nullptr, e_b1, nullptr, nullptr,
            nullptr, nullptr, nullptr, Dq, DFFq, l);
        gemm_hb<3><<<dim3(Dq / 256, TOK / 128, Ee), 512, SMEM_HB>>>(
            nullptr, e_w2, nullptr, nullptr, e_b2, nullptr, nullptr,
            nullptr, nullptr, nullptr, DFFq, Dq, l);
    }

    combine_out_kernel<<<nelem / 1024, 256>>>((float*)d_out);
    (void)in_sizes; (void)n_in; (void)out_size;
}